// round 3
// baseline (speedup 1.0000x reference)
#include <cuda_runtime.h>
#include <cstdint>

// ---------------------------------------------------------------------------
// Problem constants (shapes are fixed by the dataset)
// ---------------------------------------------------------------------------
#define MAXN 50048            // >= N=50000
#define MAXE 800000
#define MAXET (MAXE + MAXN)
#define MAXG 512

// ---------------------------------------------------------------------------
// Device scratch (static allocation — no cudaMalloc allowed)
// ---------------------------------------------------------------------------
__device__ __align__(16) float    g_bufA[(size_t)MAXN * 128]; // GEMM outputs (transformed feats)
__device__ __align__(16) float    g_bufB[(size_t)MAXN * 128]; // aggregation accumulator / layer output
__device__ float    g_deg[MAXN];
__device__ float    g_dis[MAXN];
__device__ float    g_als[MAXN * 2];
__device__ float    g_ald[MAXN * 2];
__device__ unsigned g_emax[MAXN * 2];
__device__ float    g_den[MAXN * 2];
__device__ float    g_eval[(size_t)MAXET * 2];
__device__ __align__(16) float    g_sums[MAXG * 64];
__device__ float    g_cnt[MAXG];

// ---------------------------------------------------------------------------
// Ordered-float encoding for atomicMax on floats (incl. negatives)
// ---------------------------------------------------------------------------
__device__ __forceinline__ unsigned fenc(float f) {
    unsigned u = __float_as_uint(f);
    return (u & 0x80000000u) ? ~u : (u | 0x80000000u);
}
__device__ __forceinline__ float fdec(unsigned u) {
    return __uint_as_float((u & 0x80000000u) ? (u & 0x7fffffffu) : ~u);
}

// ---------------------------------------------------------------------------
// Tiled SGEMM: C[M,N] = A[M,K] @ B[K,N].  K in {64,128}, N in {64,128}.
// BM=BN=64, BK=16, 256 threads, 4x4 per thread.
// ---------------------------------------------------------------------------
__global__ void sgemm_kernel(const float* __restrict__ A, const float* __restrict__ B,
                             float* __restrict__ C, int M, int N, int K) {
    __shared__ float As[16][65];
    __shared__ float Bs[16][65];
    const int bm = blockIdx.y * 64;
    const int bn = blockIdx.x * 64;
    const int tid = threadIdx.x;
    const int tx = tid & 15, ty = tid >> 4;
    float acc[4][4] = {};
    for (int k0 = 0; k0 < K; k0 += 16) {
        // A tile: 64 rows x 16 k
        #pragma unroll
        for (int i = tid; i < 64 * 16; i += 256) {
            int r = i >> 4, c = i & 15;
            int row = bm + r;
            As[c][r] = (row < M) ? A[(size_t)row * K + k0 + c] : 0.0f;
        }
        // B tile: 16 k x 64 cols
        #pragma unroll
        for (int i = tid; i < 16 * 64; i += 256) {
            int r = i >> 6, c = i & 63;
            Bs[r][c] = B[(size_t)(k0 + r) * N + bn + c];
        }
        __syncthreads();
        #pragma unroll
        for (int k = 0; k < 16; k++) {
            float a[4], b[4];
            #pragma unroll
            for (int i = 0; i < 4; i++) a[i] = As[k][ty * 4 + i];
            #pragma unroll
            for (int j = 0; j < 4; j++) b[j] = Bs[k][tx * 4 + j];
            #pragma unroll
            for (int i = 0; i < 4; i++)
                #pragma unroll
                for (int j = 0; j < 4; j++)
                    acc[i][j] = fmaf(a[i], b[j], acc[i][j]);
        }
        __syncthreads();
    }
    #pragma unroll
    for (int i = 0; i < 4; i++) {
        int row = bm + ty * 4 + i;
        if (row < M) {
            #pragma unroll
            for (int j = 0; j < 4; j++)
                C[(size_t)row * N + bn + tx * 4 + j] = acc[i][j];
        }
    }
}

// ---------------------------------------------------------------------------
// GCN layer pieces
// ---------------------------------------------------------------------------
__global__ void deg_kernel(const int* __restrict__ dst, int E, int n) {
    int i = blockIdx.x * blockDim.x + threadIdx.x;
    if (i >= E + n) return;
    int d = (i < E) ? dst[i] : (i - E);
    atomicAdd(&g_deg[d], 1.0f);
}

__global__ void dis_kernel(int n) {
    int i = blockIdx.x * blockDim.x + threadIdx.x;
    if (i < n) g_dis[i] = rsqrtf(g_deg[i]);   // deg >= 1 (self-loop)
}

// 16 threads / edge, float4 per thread (64 features)
__global__ void gcn_agg_kernel(const int* __restrict__ src,
                               const int* __restrict__ dst, int E, int n) {
    int t = blockIdx.x * blockDim.x + threadIdx.x;
    int e = t >> 4, lane = t & 15;
    if (e >= E + n) return;
    int s, d;
    if (e < E) { s = src[e]; d = dst[e]; } else { s = d = e - E; }
    float w = g_dis[s] * g_dis[d];
    const float4 v = *(const float4*)&g_bufA[(size_t)s * 64 + lane * 4];
    float* o = &g_bufB[(size_t)d * 64 + lane * 4];
    atomicAdd(o + 0, v.x * w);
    atomicAdd(o + 1, v.y * w);
    atomicAdd(o + 2, v.z * w);
    atomicAdd(o + 3, v.w * w);
}

__global__ void gcn_fin_kernel(const float* __restrict__ b1, int n) {
    int i = blockIdx.x * blockDim.x + threadIdx.x;
    if (i >= n * 64) return;
    float v = g_bufB[i] + b1[i & 63];
    g_bufB[i] = v > 0.0f ? v : 0.0f;
}

// ---------------------------------------------------------------------------
// GAT layer pieces (templated on heads H and per-head features F)
// ---------------------------------------------------------------------------
template <int H, int F>
__global__ void gat_al_kernel(const float* __restrict__ a_src,
                              const float* __restrict__ a_dst, int n) {
    int i = blockIdx.x * blockDim.x + threadIdx.x;
    if (i >= n * H) return;
    int node = i / H, hd = i % H;
    const float* hp = &g_bufA[(size_t)node * (H * F) + hd * F];
    float s = 0.0f, d = 0.0f;
    #pragma unroll
    for (int f = 0; f < F; f++) {
        float v = hp[f];
        s = fmaf(v, a_src[hd * F + f], s);
        d = fmaf(v, a_dst[hd * F + f], d);
    }
    g_als[i] = s;
    g_ald[i] = d;
}

template <int H>
__global__ void gat_edge_max_kernel(const int* __restrict__ src,
                                    const int* __restrict__ dst, int E, int n) {
    int t = blockIdx.x * blockDim.x + threadIdx.x;
    int e = t / H, hd = t % H;
    if (e >= E + n) return;
    int s, d;
    if (e < E) { s = src[e]; d = dst[e]; } else { s = d = e - E; }
    float v = g_als[s * H + hd] + g_ald[d * H + hd];
    v = v > 0.0f ? v : 0.2f * v;                 // leaky relu 0.2
    g_eval[(size_t)e * H + hd] = v;
    atomicMax(&g_emax[d * H + hd], fenc(v));
}

// Fused: acc[dst] += exp(e - max) * h[src], den[dst] += exp(e - max)
template <int H, int F>
__global__ void gat_edge_acc_kernel(const int* __restrict__ src,
                                    const int* __restrict__ dst, int E, int n) {
    constexpr int LANES = (H * F) / 4;
    int t = blockIdx.x * blockDim.x + threadIdx.x;
    int e = t / LANES, lane = t % LANES;
    if (e >= E + n) return;
    int s, d;
    if (e < E) { s = src[e]; d = dst[e]; } else { s = d = e - E; }
    int hd = (lane * 4) / F;
    float ex = expf(g_eval[(size_t)e * H + hd] - fdec(g_emax[d * H + hd]));
    if ((lane * 4) % F == 0) atomicAdd(&g_den[d * H + hd], ex);
    const float4 v = *(const float4*)&g_bufA[(size_t)s * (H * F) + lane * 4];
    float* o = &g_bufB[(size_t)d * (H * F) + lane * 4];
    atomicAdd(o + 0, v.x * ex);
    atomicAdd(o + 1, v.y * ex);
    atomicAdd(o + 2, v.z * ex);
    atomicAdd(o + 3, v.w * ex);
}

__global__ void gat2_fin_kernel(const float* __restrict__ b2, int n) {
    int i = blockIdx.x * blockDim.x + threadIdx.x;
    if (i >= n * 128) return;
    int node = i >> 7, j = i & 127, hd = j >> 6;
    float v = g_bufB[i] / g_den[node * 2 + hd] + b2[j];
    g_bufB[i] = v > 0.0f ? v : 0.0f;
}

__global__ void gat3_fin_kernel(const float* __restrict__ b3, int n) {
    int i = blockIdx.x * blockDim.x + threadIdx.x;
    if (i >= n * 64) return;
    int node = i >> 6;
    g_bufB[i] = g_bufB[i] / g_den[node] + b3[i & 63];   // heads=1, mean == identity
}

// ---------------------------------------------------------------------------
// Pooling + classifier
// ---------------------------------------------------------------------------
__global__ void pool_kernel(const int* __restrict__ batch, int n) {
    int t = blockIdx.x * blockDim.x + threadIdx.x;
    int node = t >> 4, lane = t & 15;
    if (node >= n) return;
    int g = batch[node];
    const float4 v = *(const float4*)&g_bufB[(size_t)node * 64 + lane * 4];
    float* o = &g_sums[g * 64 + lane * 4];
    atomicAdd(o + 0, v.x);
    atomicAdd(o + 1, v.y);
    atomicAdd(o + 2, v.z);
    atomicAdd(o + 3, v.w);
    if (lane == 0) atomicAdd(&g_cnt[g], 1.0f);
}

__global__ void final_kernel(const float* __restrict__ Wfc, const float* __restrict__ bfc,
                             float* __restrict__ out, int G) {
    int g = blockIdx.x * blockDim.x + threadIdx.x;
    if (g >= G) return;
    float c = fmaxf(g_cnt[g], 1.0f);
    float l0 = bfc[0], l1 = bfc[1];
    #pragma unroll
    for (int f = 0; f < 64; f++) {
        float p = g_sums[g * 64 + f] / c;
        l0 = fmaf(p, Wfc[f * 2 + 0], l0);
        l1 = fmaf(p, Wfc[f * 2 + 1], l1);
    }
    float m = fmaxf(l0, l1);
    float lse = m + logf(expf(l0 - m) + expf(l1 - m));
    out[2 * g + 0] = l0 - lse;
    out[2 * g + 1] = l1 - lse;
}

// ---------------------------------------------------------------------------
// Host launcher
// ---------------------------------------------------------------------------
extern "C" void kernel_launch(void* const* d_in, const int* in_sizes, int n_in,
                              void* d_out, int out_size) {
    const float* x    = (const float*)d_in[0];
    const int*   ei   = (const int*)d_in[1];
    const int*   bat  = (const int*)d_in[2];
    const float* W1   = (const float*)d_in[3];
    const float* b1   = (const float*)d_in[4];
    const float* W2   = (const float*)d_in[5];
    const float* as2  = (const float*)d_in[6];
    const float* ad2  = (const float*)d_in[7];
    const float* b2   = (const float*)d_in[8];
    const float* W3   = (const float*)d_in[9];
    const float* as3  = (const float*)d_in[10];
    const float* ad3  = (const float*)d_in[11];
    const float* b3   = (const float*)d_in[12];
    const float* Wfc  = (const float*)d_in[13];
    const float* bfc  = (const float*)d_in[14];

    const int n  = in_sizes[0] / 128;   // 50000
    const int E  = in_sizes[1] / 2;     // 800000
    const int G  = out_size / 2;        // 512
    const int* src = ei;
    const int* dst = ei + E;
    const int ET = E + n;

    void *pBufA, *pBufB, *pDeg, *pEmax, *pDen, *pSums, *pCnt;
    cudaGetSymbolAddress(&pBufA, g_bufA);
    cudaGetSymbolAddress(&pBufB, g_bufB);
    cudaGetSymbolAddress(&pDeg,  g_deg);
    cudaGetSymbolAddress(&pEmax, g_emax);
    cudaGetSymbolAddress(&pDen,  g_den);
    cudaGetSymbolAddress(&pSums, g_sums);
    cudaGetSymbolAddress(&pCnt,  g_cnt);

    const int TB = 256;
    auto cdiv = [](long long a, long long b) { return (int)((a + b - 1) / b); };

    // ===== Layer 1: GCNConv(128 -> 64), relu =====
    cudaMemsetAsync(pDeg, 0, (size_t)n * sizeof(float), 0);
    cudaMemsetAsync(pBufB, 0, (size_t)n * 64 * sizeof(float), 0);
    sgemm_kernel<<<dim3(1, cdiv(n, 64)), TB>>>(x, W1, (float*)pBufA, n, 64, 128);
    deg_kernel<<<cdiv(ET, TB), TB>>>(dst, E, n);
    dis_kernel<<<cdiv(n, TB), TB>>>(n);
    gcn_agg_kernel<<<cdiv((long long)ET * 16, TB), TB>>>(src, dst, E, n);
    gcn_fin_kernel<<<cdiv((long long)n * 64, TB), TB>>>(b1, n);

    // ===== Layer 2: GATConv(64 -> 64, heads=2, concat), relu =====
    sgemm_kernel<<<dim3(2, cdiv(n, 64)), TB>>>((const float*)pBufB, W2, (float*)pBufA, n, 128, 64);
    gat_al_kernel<2, 64><<<cdiv((long long)n * 2, TB), TB>>>(as2, ad2, n);
    cudaMemsetAsync(pEmax, 0, (size_t)n * 2 * sizeof(unsigned), 0);
    cudaMemsetAsync(pDen,  0, (size_t)n * 2 * sizeof(float), 0);
    cudaMemsetAsync(pBufB, 0, (size_t)n * 128 * sizeof(float), 0);
    gat_edge_max_kernel<2><<<cdiv((long long)ET * 2, TB), TB>>>(src, dst, E, n);
    gat_edge_acc_kernel<2, 64><<<cdiv((long long)ET * 32, TB), TB>>>(src, dst, E, n);
    gat2_fin_kernel<<<cdiv((long long)n * 128, TB), TB>>>(b2, n);

    // ===== Layer 3: GATConv(128 -> 64, heads=1, mean) =====
    sgemm_kernel<<<dim3(1, cdiv(n, 64)), TB>>>((const float*)pBufB, W3, (float*)pBufA, n, 64, 128);
    gat_al_kernel<1, 64><<<cdiv(n, TB), TB>>>(as3, ad3, n);
    cudaMemsetAsync(pEmax, 0, (size_t)n * sizeof(unsigned), 0);
    cudaMemsetAsync(pDen,  0, (size_t)n * sizeof(float), 0);
    cudaMemsetAsync(pBufB, 0, (size_t)n * 64 * sizeof(float), 0);
    gat_edge_max_kernel<1><<<cdiv(ET, TB), TB>>>(src, dst, E, n);
    gat_edge_acc_kernel<1, 64><<<cdiv((long long)ET * 16, TB), TB>>>(src, dst, E, n);
    gat3_fin_kernel<<<cdiv((long long)n * 64, TB), TB>>>(b3, n);

    // ===== Mean pool + FC + log_softmax =====
    cudaMemsetAsync(pSums, 0, (size_t)G * 64 * sizeof(float), 0);
    cudaMemsetAsync(pCnt,  0, (size_t)G * sizeof(float), 0);
    pool_kernel<<<cdiv((long long)n * 16, TB), TB>>>(bat, n);
    final_kernel<<<cdiv(G, TB), TB>>>(Wfc, bfc, (float*)d_out, G);
}

// round 4
// speedup vs baseline: 1.8196x; 1.8196x over previous
#include <cuda_runtime.h>
#include <cstdint>

// ---------------------------------------------------------------------------
// Problem constants (shapes fixed by the dataset)
// ---------------------------------------------------------------------------
#define MAXN 50048            // >= N=50000
#define MAXE 800000
#define MAXG 512

// ---------------------------------------------------------------------------
// Device scratch (static allocation — no cudaMalloc allowed)
// ---------------------------------------------------------------------------
__device__ __align__(16) float g_bufA[(size_t)MAXN * 128]; // GEMM outputs (transformed feats)
__device__ __align__(16) float g_bufB[(size_t)MAXN * 128]; // layer outputs
__device__ int   g_degi[MAXN];
__device__ int   g_rowptr[MAXN + 1];
__device__ int   g_cursor[MAXN];
__device__ int   g_col[MAXE];
__device__ float g_dis[MAXN];
__device__ float g_als[MAXN * 2];
__device__ float g_ald[MAXN * 2];
__device__ __align__(16) float g_sums[MAXG * 64];
__device__ float g_cnt[MAXG];

// ---------------------------------------------------------------------------
// Tiled SGEMM: C[M,N] = A[M,K] @ B[K,N]. BM=BN=64, BK=16, 256 thr, 4x4/thread.
// ---------------------------------------------------------------------------
__global__ void sgemm_kernel(const float* __restrict__ A, const float* __restrict__ B,
                             float* __restrict__ C, int M, int N, int K) {
    __shared__ float As[16][65];
    __shared__ float Bs[16][65];
    const int bm = blockIdx.y * 64;
    const int bn = blockIdx.x * 64;
    const int tid = threadIdx.x;
    const int tx = tid & 15, ty = tid >> 4;
    float acc[4][4] = {};
    for (int k0 = 0; k0 < K; k0 += 16) {
        #pragma unroll
        for (int i = tid; i < 64 * 16; i += 256) {
            int r = i >> 4, c = i & 15;
            int row = bm + r;
            As[c][r] = (row < M) ? A[(size_t)row * K + k0 + c] : 0.0f;
        }
        #pragma unroll
        for (int i = tid; i < 16 * 64; i += 256) {
            int r = i >> 6, c = i & 63;
            Bs[r][c] = B[(size_t)(k0 + r) * N + bn + c];
        }
        __syncthreads();
        #pragma unroll
        for (int k = 0; k < 16; k++) {
            float a[4], b[4];
            #pragma unroll
            for (int i = 0; i < 4; i++) a[i] = As[k][ty * 4 + i];
            #pragma unroll
            for (int j = 0; j < 4; j++) b[j] = Bs[k][tx * 4 + j];
            #pragma unroll
            for (int i = 0; i < 4; i++)
                #pragma unroll
                for (int j = 0; j < 4; j++)
                    acc[i][j] = fmaf(a[i], b[j], acc[i][j]);
        }
        __syncthreads();
    }
    #pragma unroll
    for (int i = 0; i < 4; i++) {
        int row = bm + ty * 4 + i;
        if (row < M) {
            #pragma unroll
            for (int j = 0; j < 4; j++)
                C[(size_t)row * N + bn + tx * 4 + j] = acc[i][j];
        }
    }
}

// ---------------------------------------------------------------------------
// CSR build (dst-indexed, real edges only; self-loops handled inline later)
// ---------------------------------------------------------------------------
__global__ void degi_kernel(const int* __restrict__ dst, int E) {
    int i = blockIdx.x * blockDim.x + threadIdx.x;
    if (i < E) atomicAdd(&g_degi[dst[i]], 1);
}

__global__ void dis_kernel(int n) {
    int i = blockIdx.x * blockDim.x + threadIdx.x;
    if (i < n) g_dis[i] = rsqrtf((float)(g_degi[i] + 1));  // +1 self-loop
}

// single block, 1024 threads: exclusive scan of g_degi -> g_rowptr, g_cursor
__global__ void scan_kernel(int n) {
    __shared__ int sums[1024];
    const int t = threadIdx.x;
    const int chunk = (n + 1023) / 1024;
    const int start = t * chunk;
    const int end = min(start + chunk, n);
    int s = 0;
    for (int i = start; i < end; i++) s += g_degi[i];
    sums[t] = s;
    __syncthreads();
    for (int off = 1; off < 1024; off <<= 1) {
        int v = (t >= off) ? sums[t - off] : 0;
        __syncthreads();
        sums[t] += v;
        __syncthreads();
    }
    int excl = (t == 0) ? 0 : sums[t - 1];
    for (int i = start; i < end; i++) {
        g_rowptr[i] = excl;
        g_cursor[i] = excl;
        excl += g_degi[i];
    }
    if (t == 1023) g_rowptr[n] = sums[1023];
}

__global__ void csr_fill_kernel(const int* __restrict__ src,
                                const int* __restrict__ dst, int E) {
    int e = blockIdx.x * blockDim.x + threadIdx.x;
    if (e >= E) return;
    int pos = atomicAdd(&g_cursor[dst[e]], 1);
    g_col[pos] = src[e];
}

// ---------------------------------------------------------------------------
// GCN aggregation: warp per node, gather over CSR, self-loop + bias + relu fused
// ---------------------------------------------------------------------------
__global__ void gcn_gather_kernel(const float* __restrict__ b1, int n) {
    int w = (blockIdx.x * blockDim.x + threadIdx.x) >> 5;
    int lane = threadIdx.x & 31;
    if (w >= n) return;
    const int d = w;
    const float dd = g_dis[d];
    const float2 sv = *(const float2*)&g_bufA[(size_t)d * 64 + lane * 2];
    float ax = dd * dd * sv.x;
    float ay = dd * dd * sv.y;
    const int beg = g_rowptr[d], end = g_rowptr[d + 1];
    for (int j = beg; j < end; j++) {
        int s = g_col[j];
        float ws = g_dis[s] * dd;
        const float2 v = *(const float2*)&g_bufA[(size_t)s * 64 + lane * 2];
        ax = fmaf(ws, v.x, ax);
        ay = fmaf(ws, v.y, ay);
    }
    ax += b1[lane * 2];
    ay += b1[lane * 2 + 1];
    float2 o;
    o.x = ax > 0.0f ? ax : 0.0f;
    o.y = ay > 0.0f ? ay : 0.0f;
    *(float2*)&g_bufB[(size_t)d * 64 + lane * 2] = o;
}

// ---------------------------------------------------------------------------
// GAT attention logits per node/head
// ---------------------------------------------------------------------------
template <int H, int F>
__global__ void gat_al_kernel(const float* __restrict__ a_src,
                              const float* __restrict__ a_dst, int n) {
    int i = blockIdx.x * blockDim.x + threadIdx.x;
    if (i >= n * H) return;
    int node = i / H, hd = i % H;
    const float* hp = &g_bufA[(size_t)node * (H * F) + hd * F];
    float s = 0.0f, d = 0.0f;
    #pragma unroll
    for (int f = 0; f < F; f++) {
        float v = hp[f];
        s = fmaf(v, a_src[hd * F + f], s);
        d = fmaf(v, a_dst[hd * F + f], d);
    }
    g_als[i] = s;
    g_ald[i] = d;
}

// ---------------------------------------------------------------------------
// GAT aggregation: warp per node, online softmax over CSR, fully fused.
// ---------------------------------------------------------------------------
template <int H, int F, bool RELU>
__global__ void gat_gather_kernel(const float* __restrict__ bias, int n,
                                  float* __restrict__ out) {
    constexpr int HF = H * F;
    constexpr int VPL = HF / 32;          // values per lane (2 or 4)
    int w = (blockIdx.x * blockDim.x + threadIdx.x) >> 5;
    int lane = threadIdx.x & 31;
    if (w >= n) return;
    const int d = w;
    const int hd = (lane * VPL) / F;      // this lane's head

    float ald_d[H], m[H], l[H];
    #pragma unroll
    for (int h = 0; h < H; h++) {
        ald_d[h] = g_ald[d * H + h];
        float v = g_als[d * H + h] + ald_d[h];
        v = v > 0.0f ? v : 0.2f * v;      // leaky relu
        m[h] = v;
        l[h] = 1.0f;
    }

    // self-loop contribution (exp(v - m) = 1)
    float acc[VPL];
    {
        const float* sp = &g_bufA[(size_t)d * HF + lane * VPL];
        if (VPL == 4) {
            const float4 v = *(const float4*)sp;
            acc[0] = v.x; acc[1] = v.y; acc[2] = v.z; acc[3] = v.w;
        } else {
            const float2 v = *(const float2*)sp;
            acc[0] = v.x; acc[1] = v.y;
        }
    }

    const int beg = g_rowptr[d], end = g_rowptr[d + 1];
    for (int j = beg; j < end; j++) {
        int s = g_col[j];
        float r[H], ex[H];
        #pragma unroll
        for (int h = 0; h < H; h++) {
            float v = g_als[s * H + h] + ald_d[h];
            v = v > 0.0f ? v : 0.2f * v;
            float mn = fmaxf(m[h], v);
            r[h]  = __expf(m[h] - mn);
            ex[h] = __expf(v - mn);
            l[h] = l[h] * r[h] + ex[h];
            m[h] = mn;
        }
        float rr = r[0], ee = ex[0];
        if (H == 2 && hd == 1) { rr = r[1]; ee = ex[1]; }
        const float* sp = &g_bufA[(size_t)s * HF + lane * VPL];
        if (VPL == 4) {
            const float4 v = *(const float4*)sp;
            acc[0] = fmaf(acc[0], rr, ee * v.x);
            acc[1] = fmaf(acc[1], rr, ee * v.y);
            acc[2] = fmaf(acc[2], rr, ee * v.z);
            acc[3] = fmaf(acc[3], rr, ee * v.w);
        } else {
            const float2 v = *(const float2*)sp;
            acc[0] = fmaf(acc[0], rr, ee * v.x);
            acc[1] = fmaf(acc[1], rr, ee * v.y);
        }
    }

    const float inv = 1.0f / ((H == 2 && hd == 1) ? l[1] : l[0]);
    #pragma unroll
    for (int i = 0; i < VPL; i++) {
        float v = acc[i] * inv + bias[lane * VPL + i];
        if (RELU) v = v > 0.0f ? v : 0.0f;
        acc[i] = v;
    }
    float* op = &out[(size_t)d * HF + lane * VPL];
    if (VPL == 4) {
        float4 o; o.x = acc[0]; o.y = acc[1]; o.z = acc[2]; o.w = acc[3];
        *(float4*)op = o;
    } else {
        float2 o; o.x = acc[0]; o.y = acc[1];
        *(float2*)op = o;
    }
}

// ---------------------------------------------------------------------------
// Pooling + classifier
// ---------------------------------------------------------------------------
__global__ void pool_kernel(const int* __restrict__ batch, int n) {
    int t = blockIdx.x * blockDim.x + threadIdx.x;
    int node = t >> 4, lane = t & 15;
    if (node >= n) return;
    int g = batch[node];
    const float4 v = *(const float4*)&g_bufB[(size_t)node * 64 + lane * 4];
    float* o = &g_sums[g * 64 + lane * 4];
    atomicAdd(o + 0, v.x);
    atomicAdd(o + 1, v.y);
    atomicAdd(o + 2, v.z);
    atomicAdd(o + 3, v.w);
    if (lane == 0) atomicAdd(&g_cnt[g], 1.0f);
}

__global__ void final_kernel(const float* __restrict__ Wfc, const float* __restrict__ bfc,
                             float* __restrict__ out, int G) {
    int g = blockIdx.x * blockDim.x + threadIdx.x;
    if (g >= G) return;
    float c = fmaxf(g_cnt[g], 1.0f);
    float l0 = bfc[0], l1 = bfc[1];
    #pragma unroll
    for (int f = 0; f < 64; f++) {
        float p = g_sums[g * 64 + f] / c;
        l0 = fmaf(p, Wfc[f * 2 + 0], l0);
        l1 = fmaf(p, Wfc[f * 2 + 1], l1);
    }
    float m = fmaxf(l0, l1);
    float lse = m + logf(expf(l0 - m) + expf(l1 - m));
    out[2 * g + 0] = l0 - lse;
    out[2 * g + 1] = l1 - lse;
}

// ---------------------------------------------------------------------------
// Host launcher
// ---------------------------------------------------------------------------
extern "C" void kernel_launch(void* const* d_in, const int* in_sizes, int n_in,
                              void* d_out, int out_size) {
    const float* x    = (const float*)d_in[0];
    const int*   ei   = (const int*)d_in[1];
    const int*   bat  = (const int*)d_in[2];
    const float* W1   = (const float*)d_in[3];
    const float* b1   = (const float*)d_in[4];
    const float* W2   = (const float*)d_in[5];
    const float* as2  = (const float*)d_in[6];
    const float* ad2  = (const float*)d_in[7];
    const float* b2   = (const float*)d_in[8];
    const float* W3   = (const float*)d_in[9];
    const float* as3  = (const float*)d_in[10];
    const float* ad3  = (const float*)d_in[11];
    const float* b3   = (const float*)d_in[12];
    const float* Wfc  = (const float*)d_in[13];
    const float* bfc  = (const float*)d_in[14];

    const int n  = in_sizes[0] / 128;   // 50000
    const int E  = in_sizes[1] / 2;     // 800000
    const int G  = out_size / 2;        // 512
    const int* src = ei;
    const int* dst = ei + E;

    void *pBufA, *pBufB, *pDegi, *pSums, *pCnt;
    cudaGetSymbolAddress(&pBufA, g_bufA);
    cudaGetSymbolAddress(&pBufB, g_bufB);
    cudaGetSymbolAddress(&pDegi, g_degi);
    cudaGetSymbolAddress(&pSums, g_sums);
    cudaGetSymbolAddress(&pCnt,  g_cnt);

    const int TB = 256;
    auto cdiv = [](long long a, long long b) { return (int)((a + b - 1) / b); };

    // ===== CSR build (reused by all 3 layers) + layer-1 GEMM in parallel =====
    cudaMemsetAsync(pDegi, 0, (size_t)n * sizeof(int), 0);
    sgemm_kernel<<<dim3(1, cdiv(n, 64)), TB>>>(x, W1, (float*)pBufA, n, 64, 128);
    degi_kernel<<<cdiv(E, TB), TB>>>(dst, E);
    dis_kernel<<<cdiv(n, TB), TB>>>(n);
    scan_kernel<<<1, 1024>>>(n);
    csr_fill_kernel<<<cdiv(E, TB), TB>>>(src, dst, E);

    // ===== Layer 1: GCNConv(128 -> 64) + relu (fused) =====
    gcn_gather_kernel<<<cdiv((long long)n * 32, TB), TB>>>(b1, n);

    // ===== Layer 2: GATConv(64 -> 64, heads=2, concat) + relu =====
    sgemm_kernel<<<dim3(2, cdiv(n, 64)), TB>>>((const float*)pBufB, W2, (float*)pBufA, n, 128, 64);
    gat_al_kernel<2, 64><<<cdiv((long long)n * 2, TB), TB>>>(as2, ad2, n);
    gat_gather_kernel<2, 64, true><<<cdiv((long long)n * 32, TB), TB>>>(b2, n, (float*)pBufB);

    // ===== Layer 3: GATConv(128 -> 64, heads=1, mean) =====
    sgemm_kernel<<<dim3(1, cdiv(n, 64)), TB>>>((const float*)pBufB, W3, (float*)pBufA, n, 64, 128);
    gat_al_kernel<1, 64><<<cdiv(n, TB), TB>>>(as3, ad3, n);
    gat_gather_kernel<1, 64, false><<<cdiv((long long)n * 32, TB), TB>>>(b3, n, (float*)pBufB);

    // ===== Mean pool + FC + log_softmax =====
    cudaMemsetAsync(pSums, 0, (size_t)G * 64 * sizeof(float), 0);
    cudaMemsetAsync(pCnt,  0, (size_t)G * sizeof(float), 0);
    pool_kernel<<<cdiv((long long)n * 16, TB), TB>>>(bat, n);
    final_kernel<<<cdiv(G, TB), TB>>>(Wfc, bfc, (float*)d_out, G);
}

// round 5
// speedup vs baseline: 2.1154x; 1.1626x over previous
#include <cuda_runtime.h>
#include <cstdint>

// ---------------------------------------------------------------------------
// Problem constants (shapes fixed by the dataset)
// ---------------------------------------------------------------------------
#define MAXN 50048            // >= N=50000
#define MAXE 800000
#define MAXG 512
#define SCAN_CHUNK 4096       // elements per scan block (512 thr * 8)
#define MAXSB ((MAXN + SCAN_CHUNK - 1) / SCAN_CHUNK)

// ---------------------------------------------------------------------------
// Device scratch (static allocation — no cudaMalloc allowed)
// ---------------------------------------------------------------------------
__device__ __align__(16) float g_bufA[(size_t)MAXN * 128]; // GEMM outputs (transformed feats)
__device__ __align__(16) float g_bufB[(size_t)MAXN * 128]; // layer outputs
__device__ int   g_degi[MAXN];
__device__ int   g_rowptr[MAXN + 1];
__device__ int   g_cursor[MAXN];
__device__ int   g_col[MAXE];
__device__ int   g_bsum[MAXSB];
__device__ int   g_boff[MAXSB];
__device__ float g_dis[MAXN];
__device__ float g_als[MAXN * 2];
__device__ float g_ald[MAXN * 2];
__device__ __align__(16) float g_sums[MAXG * 64];
__device__ float g_cnt[MAXG];

// ---------------------------------------------------------------------------
// Tiled SGEMM: C[M,N] = A[M,K] @ B[K,N]. BM=BN=64, BK=16, 256 thr, 4x4/thread.
// ---------------------------------------------------------------------------
__global__ void sgemm_kernel(const float* __restrict__ A, const float* __restrict__ B,
                             float* __restrict__ C, int M, int N, int K) {
    __shared__ float As[16][65];
    __shared__ float Bs[16][65];
    const int bm = blockIdx.y * 64;
    const int bn = blockIdx.x * 64;
    const int tid = threadIdx.x;
    const int tx = tid & 15, ty = tid >> 4;
    float acc[4][4] = {};
    for (int k0 = 0; k0 < K; k0 += 16) {
        #pragma unroll
        for (int i = tid; i < 64 * 16; i += 256) {
            int r = i >> 4, c = i & 15;
            int row = bm + r;
            As[c][r] = (row < M) ? A[(size_t)row * K + k0 + c] : 0.0f;
        }
        #pragma unroll
        for (int i = tid; i < 16 * 64; i += 256) {
            int r = i >> 6, c = i & 63;
            Bs[r][c] = B[(size_t)(k0 + r) * N + bn + c];
        }
        __syncthreads();
        #pragma unroll
        for (int k = 0; k < 16; k++) {
            float a[4], b[4];
            #pragma unroll
            for (int i = 0; i < 4; i++) a[i] = As[k][ty * 4 + i];
            #pragma unroll
            for (int j = 0; j < 4; j++) b[j] = Bs[k][tx * 4 + j];
            #pragma unroll
            for (int i = 0; i < 4; i++)
                #pragma unroll
                for (int j = 0; j < 4; j++)
                    acc[i][j] = fmaf(a[i], b[j], acc[i][j]);
        }
        __syncthreads();
    }
    #pragma unroll
    for (int i = 0; i < 4; i++) {
        int row = bm + ty * 4 + i;
        if (row < M) {
            #pragma unroll
            for (int j = 0; j < 4; j++)
                C[(size_t)row * N + bn + tx * 4 + j] = acc[i][j];
        }
    }
}

// ---------------------------------------------------------------------------
// CSR build (dst-indexed, real edges only; self-loops handled inline later)
// ---------------------------------------------------------------------------
__global__ void degi_kernel(const int* __restrict__ dst, int E) {
    int i = blockIdx.x * blockDim.x + threadIdx.x;
    if (i < E) atomicAdd(&g_degi[dst[i]], 1);
}

// Phase 1: per-block reduction of degrees (SCAN_CHUNK elems / block)
__global__ void scan_reduce_kernel(int n) {
    __shared__ int red[512];
    const int b = blockIdx.x, t = threadIdx.x;
    const int base = b * SCAN_CHUNK;
    int s = 0;
    #pragma unroll
    for (int i = t; i < SCAN_CHUNK; i += 512) {
        int idx = base + i;
        if (idx < n) s += g_degi[idx];
    }
    red[t] = s;
    __syncthreads();
    #pragma unroll
    for (int off = 256; off > 0; off >>= 1) {
        if (t < off) red[t] += red[t + off];
        __syncthreads();
    }
    if (t == 0) g_bsum[b] = red[0];
}

// Phase 2: tiny serial exclusive scan of block sums (nb <= 13)
__global__ void scan_boff_kernel(int nb, int n, int E) {
    if (threadIdx.x == 0) {
        int acc = 0;
        for (int i = 0; i < nb; i++) { g_boff[i] = acc; acc += g_bsum[i]; }
        g_rowptr[n] = E;
    }
}

// Phase 3: per-block scan + write rowptr/cursor/dis
__global__ void scan_write_kernel(int n) {
    __shared__ int sm[512];
    const int b = blockIdx.x, t = threadIdx.x;
    const int start = b * SCAN_CHUNK + t * 8;
    int vals[8];
    int s = 0;
    #pragma unroll
    for (int i = 0; i < 8; i++) {
        int idx = start + i;
        vals[i] = (idx < n) ? g_degi[idx] : 0;
        s += vals[i];
    }
    sm[t] = s;
    __syncthreads();
    #pragma unroll
    for (int off = 1; off < 512; off <<= 1) {
        int v = (t >= off) ? sm[t - off] : 0;
        __syncthreads();
        sm[t] += v;
        __syncthreads();
    }
    int excl = g_boff[b] + ((t == 0) ? 0 : sm[t - 1]);
    #pragma unroll
    for (int i = 0; i < 8; i++) {
        int idx = start + i;
        if (idx < n) {
            g_rowptr[idx] = excl;
            g_cursor[idx] = excl;
            g_dis[idx] = rsqrtf((float)(vals[i] + 1));  // +1 self-loop
            excl += vals[i];
        }
    }
}

__global__ void csr_fill_kernel(const int* __restrict__ src,
                                const int* __restrict__ dst, int E) {
    int e = blockIdx.x * blockDim.x + threadIdx.x;
    if (e >= E) return;
    int pos = atomicAdd(&g_cursor[dst[e]], 1);
    g_col[pos] = src[e];
}

// ---------------------------------------------------------------------------
// GCN aggregation: warp per node, gather over CSR, self-loop + bias + relu fused
// ---------------------------------------------------------------------------
__global__ void gcn_gather_kernel(const float* __restrict__ b1, int n) {
    int w = (blockIdx.x * blockDim.x + threadIdx.x) >> 5;
    int lane = threadIdx.x & 31;
    if (w >= n) return;
    const int d = w;
    const float dd = g_dis[d];
    const float2 sv = *(const float2*)&g_bufA[(size_t)d * 64 + lane * 2];
    float ax = dd * dd * sv.x;
    float ay = dd * dd * sv.y;
    const int beg = g_rowptr[d], end = g_rowptr[d + 1];
    for (int j = beg; j < end; j++) {
        int s = g_col[j];
        float ws = g_dis[s] * dd;
        const float2 v = *(const float2*)&g_bufA[(size_t)s * 64 + lane * 2];
        ax = fmaf(ws, v.x, ax);
        ay = fmaf(ws, v.y, ay);
    }
    ax += b1[lane * 2];
    ay += b1[lane * 2 + 1];
    float2 o;
    o.x = ax > 0.0f ? ax : 0.0f;
    o.y = ay > 0.0f ? ay : 0.0f;
    *(float2*)&g_bufB[(size_t)d * 64 + lane * 2] = o;
}

// ---------------------------------------------------------------------------
// GAT attention logits per node/head
// ---------------------------------------------------------------------------
template <int H, int F>
__global__ void gat_al_kernel(const float* __restrict__ a_src,
                              const float* __restrict__ a_dst, int n) {
    int i = blockIdx.x * blockDim.x + threadIdx.x;
    if (i >= n * H) return;
    int node = i / H, hd = i % H;
    const float* hp = &g_bufA[(size_t)node * (H * F) + hd * F];
    float s = 0.0f, d = 0.0f;
    #pragma unroll
    for (int f = 0; f < F; f++) {
        float v = hp[f];
        s = fmaf(v, a_src[hd * F + f], s);
        d = fmaf(v, a_dst[hd * F + f], d);
    }
    g_als[i] = s;
    g_ald[i] = d;
}

// ---------------------------------------------------------------------------
// GAT aggregation: warp per node, online softmax over CSR, fully fused.
// ---------------------------------------------------------------------------
template <int H, int F, bool RELU>
__global__ void gat_gather_kernel(const float* __restrict__ bias, int n,
                                  float* __restrict__ out) {
    constexpr int HF = H * F;
    constexpr int VPL = HF / 32;          // values per lane (2 or 4)
    int w = (blockIdx.x * blockDim.x + threadIdx.x) >> 5;
    int lane = threadIdx.x & 31;
    if (w >= n) return;
    const int d = w;
    const int hd = (lane * VPL) / F;      // this lane's head

    float ald_d[H], m[H], l[H];
    #pragma unroll
    for (int h = 0; h < H; h++) {
        ald_d[h] = g_ald[d * H + h];
        float v = g_als[d * H + h] + ald_d[h];
        v = v > 0.0f ? v : 0.2f * v;      // leaky relu
        m[h] = v;
        l[h] = 1.0f;
    }

    // self-loop contribution (exp(v - m) = 1)
    float acc[VPL];
    {
        const float* sp = &g_bufA[(size_t)d * HF + lane * VPL];
        if (VPL == 4) {
            const float4 v = *(const float4*)sp;
            acc[0] = v.x; acc[1] = v.y; acc[2] = v.z; acc[3] = v.w;
        } else {
            const float2 v = *(const float2*)sp;
            acc[0] = v.x; acc[1] = v.y;
        }
    }

    const int beg = g_rowptr[d], end = g_rowptr[d + 1];
    for (int j = beg; j < end; j++) {
        int s = g_col[j];
        float r[H], ex[H];
        #pragma unroll
        for (int h = 0; h < H; h++) {
            float v = g_als[s * H + h] + ald_d[h];
            v = v > 0.0f ? v : 0.2f * v;
            float mn = fmaxf(m[h], v);
            r[h]  = __expf(m[h] - mn);
            ex[h] = __expf(v - mn);
            l[h] = l[h] * r[h] + ex[h];
            m[h] = mn;
        }
        float rr = r[0], ee = ex[0];
        if (H == 2 && hd == 1) { rr = r[1]; ee = ex[1]; }
        const float* sp = &g_bufA[(size_t)s * HF + lane * VPL];
        if (VPL == 4) {
            const float4 v = *(const float4*)sp;
            acc[0] = fmaf(acc[0], rr, ee * v.x);
            acc[1] = fmaf(acc[1], rr, ee * v.y);
            acc[2] = fmaf(acc[2], rr, ee * v.z);
            acc[3] = fmaf(acc[3], rr, ee * v.w);
        } else {
            const float2 v = *(const float2*)sp;
            acc[0] = fmaf(acc[0], rr, ee * v.x);
            acc[1] = fmaf(acc[1], rr, ee * v.y);
        }
    }

    const float inv = 1.0f / ((H == 2 && hd == 1) ? l[1] : l[0]);
    #pragma unroll
    for (int i = 0; i < VPL; i++) {
        float v = acc[i] * inv + bias[lane * VPL + i];
        if (RELU) v = v > 0.0f ? v : 0.0f;
        acc[i] = v;
    }
    float* op = &out[(size_t)d * HF + lane * VPL];
    if (VPL == 4) {
        float4 o; o.x = acc[0]; o.y = acc[1]; o.z = acc[2]; o.w = acc[3];
        *(float4*)op = o;
    } else {
        float2 o; o.x = acc[0]; o.y = acc[1];
        *(float2*)op = o;
    }
}

// ---------------------------------------------------------------------------
// Pooling + classifier
// ---------------------------------------------------------------------------
__global__ void pool_kernel(const int* __restrict__ batch, int n) {
    int t = blockIdx.x * blockDim.x + threadIdx.x;
    int node = t >> 4, lane = t & 15;
    if (node >= n) return;
    int g = batch[node];
    const float4 v = *(const float4*)&g_bufB[(size_t)node * 64 + lane * 4];
    float* o = &g_sums[g * 64 + lane * 4];
    atomicAdd(o + 0, v.x);
    atomicAdd(o + 1, v.y);
    atomicAdd(o + 2, v.z);
    atomicAdd(o + 3, v.w);
    if (lane == 0) atomicAdd(&g_cnt[g], 1.0f);
}

__global__ void final_kernel(const float* __restrict__ Wfc, const float* __restrict__ bfc,
                             float* __restrict__ out, int G) {
    int g = blockIdx.x * blockDim.x + threadIdx.x;
    if (g >= G) return;
    float c = fmaxf(g_cnt[g], 1.0f);
    float l0 = bfc[0], l1 = bfc[1];
    #pragma unroll
    for (int f = 0; f < 64; f++) {
        float p = g_sums[g * 64 + f] / c;
        l0 = fmaf(p, Wfc[f * 2 + 0], l0);
        l1 = fmaf(p, Wfc[f * 2 + 1], l1);
    }
    float m = fmaxf(l0, l1);
    float lse = m + logf(expf(l0 - m) + expf(l1 - m));
    out[2 * g + 0] = l0 - lse;
    out[2 * g + 1] = l1 - lse;
}

// ---------------------------------------------------------------------------
// Host launcher
// ---------------------------------------------------------------------------
extern "C" void kernel_launch(void* const* d_in, const int* in_sizes, int n_in,
                              void* d_out, int out_size) {
    const float* x    = (const float*)d_in[0];
    const int*   ei   = (const int*)d_in[1];
    const int*   bat  = (const int*)d_in[2];
    const float* W1   = (const float*)d_in[3];
    const float* b1   = (const float*)d_in[4];
    const float* W2   = (const float*)d_in[5];
    const float* as2  = (const float*)d_in[6];
    const float* ad2  = (const float*)d_in[7];
    const float* b2   = (const float*)d_in[8];
    const float* W3   = (const float*)d_in[9];
    const float* as3  = (const float*)d_in[10];
    const float* ad3  = (const float*)d_in[11];
    const float* b3   = (const float*)d_in[12];
    const float* Wfc  = (const float*)d_in[13];
    const float* bfc  = (const float*)d_in[14];

    const int n  = in_sizes[0] / 128;   // 50000
    const int E  = in_sizes[1] / 2;     // 800000
    const int G  = out_size / 2;        // 512
    const int* src = ei;
    const int* dst = ei + E;
    const int nb = (n + SCAN_CHUNK - 1) / SCAN_CHUNK;

    void *pBufA, *pBufB, *pDegi, *pSums, *pCnt;
    cudaGetSymbolAddress(&pBufA, g_bufA);
    cudaGetSymbolAddress(&pBufB, g_bufB);
    cudaGetSymbolAddress(&pDegi, g_degi);
    cudaGetSymbolAddress(&pSums, g_sums);
    cudaGetSymbolAddress(&pCnt,  g_cnt);

    const int TB = 256;
    auto cdiv = [](long long a, long long b) { return (int)((a + b - 1) / b); };

    // ===== CSR build (reused by all 3 layers) + layer-1 GEMM =====
    cudaMemsetAsync(pDegi, 0, (size_t)n * sizeof(int), 0);
    sgemm_kernel<<<dim3(1, cdiv(n, 64)), TB>>>(x, W1, (float*)pBufA, n, 64, 128);
    degi_kernel<<<cdiv(E, TB), TB>>>(dst, E);
    scan_reduce_kernel<<<nb, 512>>>(n);
    scan_boff_kernel<<<1, 32>>>(nb, n, E);
    scan_write_kernel<<<nb, 512>>>(n);
    csr_fill_kernel<<<cdiv(E, TB), TB>>>(src, dst, E);

    // ===== Layer 1: GCNConv(128 -> 64) + relu (fused) =====
    gcn_gather_kernel<<<cdiv((long long)n * 32, TB), TB>>>(b1, n);

    // ===== Layer 2: GATConv(64 -> 64, heads=2, concat) + relu =====
    sgemm_kernel<<<dim3(2, cdiv(n, 64)), TB>>>((const float*)pBufB, W2, (float*)pBufA, n, 128, 64);
    gat_al_kernel<2, 64><<<cdiv((long long)n * 2, TB), TB>>>(as2, ad2, n);
    gat_gather_kernel<2, 64, true><<<cdiv((long long)n * 32, TB), TB>>>(b2, n, (float*)pBufB);

    // ===== Layer 3: GATConv(128 -> 64, heads=1, mean) =====
    sgemm_kernel<<<dim3(1, cdiv(n, 64)), TB>>>((const float*)pBufB, W3, (float*)pBufA, n, 64, 128);
    gat_al_kernel<1, 64><<<cdiv(n, TB), TB>>>(as3, ad3, n);
    gat_gather_kernel<1, 64, false><<<cdiv((long long)n * 32, TB), TB>>>(b3, n, (float*)pBufB);

    // ===== Mean pool + FC + log_softmax =====
    cudaMemsetAsync(pSums, 0, (size_t)G * 64 * sizeof(float), 0);
    cudaMemsetAsync(pCnt,  0, (size_t)G * sizeof(float), 0);
    pool_kernel<<<cdiv((long long)n * 16, TB), TB>>>(bat, n);
    final_kernel<<<cdiv(G, TB), TB>>>(Wfc, bfc, (float*)d_out, G);
}

// round 7
// speedup vs baseline: 2.9116x; 1.3764x over previous
#include <cuda_runtime.h>
#include <cstdint>

// ---------------------------------------------------------------------------
// Problem constants (shapes fixed by the dataset)
// ---------------------------------------------------------------------------
#define MAXN 50048            // >= N=50000
#define MAXE 800000
#define MAXG 512
#define SCAN_CHUNK 4096       // elements per scan block (512 thr * 8)
#define MAXSB ((MAXN + SCAN_CHUNK - 1) / SCAN_CHUNK)

// ---------------------------------------------------------------------------
// Device scratch (static allocation — no cudaMalloc allowed)
// ---------------------------------------------------------------------------
__device__ __align__(16) float g_bufA[(size_t)MAXN * 128]; // GEMM outputs (transformed feats)
__device__ __align__(16) float g_bufB[(size_t)MAXN * 128]; // layer outputs
__device__ int   g_degi[MAXN];
__device__ int   g_rowptr[MAXN + 1];
__device__ int   g_cursor[MAXN];
__device__ int   g_col[MAXE];
__device__ int   g_bsum[MAXSB];
__device__ int   g_boff[MAXSB];
__device__ float g_dis[MAXN];
__device__ __align__(8) float g_als[MAXN * 2];
__device__ __align__(8) float g_ald[MAXN * 2];
__device__ __align__(16) float g_sums[MAXG * 64];
__device__ float g_cnt[MAXG];

// ---------------------------------------------------------------------------
// Tiled SGEMM: C[M,N] = A[M,K] @ B[K,N]. BM=BN=64, BK=16, 256 thr, 4x4/thread.
// H > 0: fused GAT attention-logit epilogue. Each 64-col block is one head;
// a_src/a_dst flattened index equals the global output column.
// ---------------------------------------------------------------------------
template <int H>
__global__ void sgemm_kernel(const float* __restrict__ A, const float* __restrict__ B,
                             float* __restrict__ C, int M, int N, int K,
                             const float* __restrict__ a_src,
                             const float* __restrict__ a_dst) {
    __shared__ float As[16][65];
    __shared__ float Bs[16][68];   // row stride multiple of 4 -> float4-aligned
    const int bm = blockIdx.y * 64;
    const int bn = blockIdx.x * 64;
    const int tid = threadIdx.x;
    const int tx = tid & 15, ty = tid >> 4;
    float acc[4][4] = {};
    for (int k0 = 0; k0 < K; k0 += 16) {
        // A tile: 64 rows x 16 k, float4 loads, scalar smem stores (transposed)
        {
            int r = tid >> 2, c4 = (tid & 3) * 4;
            int row = bm + r;
            float4 v = make_float4(0.f, 0.f, 0.f, 0.f);
            if (row < M) v = *(const float4*)&A[(size_t)row * K + k0 + c4];
            As[c4 + 0][r] = v.x;
            As[c4 + 1][r] = v.y;
            As[c4 + 2][r] = v.z;
            As[c4 + 3][r] = v.w;
        }
        // B tile: 16 k x 64 cols, float4 loads + float4 smem stores
        {
            int r = tid >> 4, c4 = (tid & 15) * 4;
            float4 v = *(const float4*)&B[(size_t)(k0 + r) * N + bn + c4];
            *(float4*)&Bs[r][c4] = v;
        }
        __syncthreads();
        #pragma unroll
        for (int k = 0; k < 16; k++) {
            float a[4], b[4];
            #pragma unroll
            for (int i = 0; i < 4; i++) a[i] = As[k][ty * 4 + i];
            #pragma unroll
            for (int j = 0; j < 4; j++) b[j] = Bs[k][tx * 4 + j];
            #pragma unroll
            for (int i = 0; i < 4; i++)
                #pragma unroll
                for (int j = 0; j < 4; j++)
                    acc[i][j] = fmaf(a[i], b[j], acc[i][j]);
        }
        __syncthreads();
    }
    #pragma unroll
    for (int i = 0; i < 4; i++) {
        int row = bm + ty * 4 + i;
        if (row < M) {
            #pragma unroll
            for (int j = 0; j < 4; j++)
                C[(size_t)row * N + bn + tx * 4 + j] = acc[i][j];
        }
    }
    if (H > 0) {
        // attention logits: per-row dot of this head's 64 cols with a_src/a_dst
        const int hd = bn >> 6;
        float asr[4], adr[4];
        #pragma unroll
        for (int j = 0; j < 4; j++) {
            asr[j] = a_src[bn + tx * 4 + j];
            adr[j] = a_dst[bn + tx * 4 + j];
        }
        #pragma unroll
        for (int i = 0; i < 4; i++) {
            float s = 0.f, d = 0.f;
            #pragma unroll
            for (int j = 0; j < 4; j++) {
                s = fmaf(acc[i][j], asr[j], s);
                d = fmaf(acc[i][j], adr[j], d);
            }
            // reduce across the 16 tx lanes (xor offsets < 16 stay in-group)
            #pragma unroll
            for (int off = 8; off >= 1; off >>= 1) {
                s += __shfl_xor_sync(0xffffffffu, s, off);
                d += __shfl_xor_sync(0xffffffffu, d, off);
            }
            int row = bm + ty * 4 + i;
            if (tx == 0 && row < M) {
                g_als[row * H + hd] = s;
                g_ald[row * H + hd] = d;
            }
        }
    }
}

// ---------------------------------------------------------------------------
// CSR build (dst-indexed, real edges only; self-loops handled inline later)
// ---------------------------------------------------------------------------
__global__ void degi_kernel(const int* __restrict__ dst, int E) {
    int i = blockIdx.x * blockDim.x + threadIdx.x;
    if (i < E) atomicAdd(&g_degi[dst[i]], 1);
}

__global__ void scan_reduce_kernel(int n) {
    __shared__ int red[512];
    const int b = blockIdx.x, t = threadIdx.x;
    const int base = b * SCAN_CHUNK;
    int s = 0;
    #pragma unroll
    for (int i = t; i < SCAN_CHUNK; i += 512) {
        int idx = base + i;
        if (idx < n) s += g_degi[idx];
    }
    red[t] = s;
    __syncthreads();
    #pragma unroll
    for (int off = 256; off > 0; off >>= 1) {
        if (t < off) red[t] += red[t + off];
        __syncthreads();
    }
    if (t == 0) g_bsum[b] = red[0];
}

__global__ void scan_boff_kernel(int nb, int n, int E) {
    if (threadIdx.x == 0) {
        int acc = 0;
        for (int i = 0; i < nb; i++) { g_boff[i] = acc; acc += g_bsum[i]; }
        g_rowptr[n] = E;
    }
}

__global__ void scan_write_kernel(int n) {
    __shared__ int sm[512];
    const int b = blockIdx.x, t = threadIdx.x;
    const int start = b * SCAN_CHUNK + t * 8;
    int vals[8];
    int s = 0;
    #pragma unroll
    for (int i = 0; i < 8; i++) {
        int idx = start + i;
        vals[i] = (idx < n) ? g_degi[idx] : 0;
        s += vals[i];
    }
    sm[t] = s;
    __syncthreads();
    #pragma unroll
    for (int off = 1; off < 512; off <<= 1) {
        int v = (t >= off) ? sm[t - off] : 0;
        __syncthreads();
        sm[t] += v;
        __syncthreads();
    }
    int excl = g_boff[b] + ((t == 0) ? 0 : sm[t - 1]);
    #pragma unroll
    for (int i = 0; i < 8; i++) {
        int idx = start + i;
        if (idx < n) {
            g_rowptr[idx] = excl;
            g_cursor[idx] = excl;
            g_dis[idx] = rsqrtf((float)(vals[i] + 1));  // +1 self-loop
            excl += vals[i];
        }
    }
}

__global__ void csr_fill_kernel(const int* __restrict__ src,
                                const int* __restrict__ dst, int E) {
    int e = blockIdx.x * blockDim.x + threadIdx.x;
    if (e >= E) return;
    int pos = atomicAdd(&g_cursor[dst[e]], 1);
    g_col[pos] = src[e];
}

// ---------------------------------------------------------------------------
// GCN aggregation: warp per node, warp-staged edges, 4-unrolled inner loop.
// ---------------------------------------------------------------------------
__global__ void gcn_gather_kernel(const float* __restrict__ b1, int n) {
    __shared__ int   s_col[8][32];
    __shared__ float s_wt[8][32];
    const int w = (blockIdx.x * blockDim.x + threadIdx.x) >> 5;
    const int lane = threadIdx.x & 31;
    const int wrp = threadIdx.x >> 5;
    if (w >= n) return;
    const int d = w;
    const float dd = g_dis[d];
    const float2 sv = *(const float2*)&g_bufA[(size_t)d * 64 + lane * 2];
    float ax = dd * dd * sv.x;
    float ay = dd * dd * sv.y;
    const int beg = g_rowptr[d], end = g_rowptr[d + 1];

    auto proc = [&](int k) {
        int s = s_col[wrp][k];
        float ws = s_wt[wrp][k];
        const float2 v = *(const float2*)&g_bufA[(size_t)s * 64 + lane * 2];
        ax = fmaf(ws, v.x, ax);
        ay = fmaf(ws, v.y, ay);
    };

    for (int j0 = beg; j0 < end; j0 += 32) {
        const int cnt = min(32, end - j0);
        if (lane < cnt) {
            int s = g_col[j0 + lane];
            s_col[wrp][lane] = s;
            s_wt[wrp][lane] = g_dis[s] * dd;
        }
        __syncwarp();
        int k = 0;
        for (; k + 4 <= cnt; k += 4) { proc(k); proc(k + 1); proc(k + 2); proc(k + 3); }
        for (; k < cnt; k++) proc(k);
        __syncwarp();
    }
    ax += b1[lane * 2];
    ay += b1[lane * 2 + 1];
    float2 o;
    o.x = ax > 0.0f ? ax : 0.0f;
    o.y = ay > 0.0f ? ay : 0.0f;
    *(float2*)&g_bufB[(size_t)d * 64 + lane * 2] = o;
}

// ---------------------------------------------------------------------------
// GAT aggregation: warp per node, warp-staged edges, chunk-max online softmax.
// ---------------------------------------------------------------------------
template <int H, int F, bool RELU>
__global__ void gat_gather_kernel(const float* __restrict__ bias, int n,
                                  float* __restrict__ out) {
    constexpr int HF = H * F;
    constexpr int VPL = HF / 32;          // values per lane (2 or 4)
    __shared__ int   s_col[8][32];
    __shared__ float s_e[8][H * 32];      // leaky-relu'd logits per head
    const int w = (blockIdx.x * blockDim.x + threadIdx.x) >> 5;
    const int lane = threadIdx.x & 31;
    const int wrp = threadIdx.x >> 5;
    if (w >= n) return;
    const int d = w;
    const int hd = (lane * VPL) / F;      // this lane's head

    float ald_d[H], m[H], l[H];
    #pragma unroll
    for (int h = 0; h < H; h++) {
        ald_d[h] = g_ald[d * H + h];
        float v = g_als[d * H + h] + ald_d[h];
        v = v > 0.0f ? v : 0.2f * v;      // leaky relu
        m[h] = v;
        l[h] = 1.0f;
    }

    // self-loop contribution (exp(v - m) = 1 at init)
    float acc[VPL];
    {
        const float* sp = &g_bufA[(size_t)d * HF + lane * VPL];
        if (VPL == 4) {
            const float4 v = *(const float4*)sp;
            acc[0] = v.x; acc[1] = v.y; acc[2] = v.z; acc[3] = v.w;
        } else {
            const float2 v = *(const float2*)sp;
            acc[0] = v.x; acc[1] = v.y;
        }
    }

    const int beg = g_rowptr[d], end = g_rowptr[d + 1];

    auto proc = [&](int k) {
        int s = s_col[wrp][k];
        float ex[H];
        #pragma unroll
        for (int h = 0; h < H; h++) {
            ex[h] = __expf(s_e[wrp][h * 32 + k] - m[h]);
            l[h] += ex[h];
        }
        float ee = (H == 2 && hd == 1) ? ex[1] : ex[0];
        const float* sp = &g_bufA[(size_t)s * HF + lane * VPL];
        if (VPL == 4) {
            const float4 v = *(const float4*)sp;
            acc[0] = fmaf(ee, v.x, acc[0]);
            acc[1] = fmaf(ee, v.y, acc[1]);
            acc[2] = fmaf(ee, v.z, acc[2]);
            acc[3] = fmaf(ee, v.w, acc[3]);
        } else {
            const float2 v = *(const float2*)sp;
            acc[0] = fmaf(ee, v.x, acc[0]);
            acc[1] = fmaf(ee, v.y, acc[1]);
        }
    };

    for (int j0 = beg; j0 < end; j0 += 32) {
        const int cnt = min(32, end - j0);
        float myv[H];
        #pragma unroll
        for (int h = 0; h < H; h++) myv[h] = -3.0e38f;
        if (lane < cnt) {
            int s = g_col[j0 + lane];
            s_col[wrp][lane] = s;
            #pragma unroll
            for (int h = 0; h < H; h++) {
                float v = g_als[s * H + h] + ald_d[h];
                v = v > 0.0f ? v : 0.2f * v;
                s_e[wrp][h * 32 + lane] = v;
                myv[h] = v;
            }
        }
        // chunk max per head + single rescale
        #pragma unroll
        for (int h = 0; h < H; h++) {
            float cm = myv[h];
            #pragma unroll
            for (int off = 16; off >= 1; off >>= 1)
                cm = fmaxf(cm, __shfl_xor_sync(0xffffffffu, cm, off));
            if (cm > m[h]) {
                float r = __expf(m[h] - cm);
                l[h] *= r;
                if (h == ((H == 2) ? hd : 0)) {
                    #pragma unroll
                    for (int i = 0; i < VPL; i++) acc[i] *= r;
                }
                m[h] = cm;
            }
        }
        __syncwarp();
        int k = 0;
        for (; k + 4 <= cnt; k += 4) { proc(k); proc(k + 1); proc(k + 2); proc(k + 3); }
        for (; k < cnt; k++) proc(k);
        __syncwarp();
    }

    const float inv = 1.0f / ((H == 2 && hd == 1) ? l[1] : l[0]);
    #pragma unroll
    for (int i = 0; i < VPL; i++) {
        float v = acc[i] * inv + bias[lane * VPL + i];
        if (RELU) v = v > 0.0f ? v : 0.0f;
        acc[i] = v;
    }
    float* op = &out[(size_t)d * HF + lane * VPL];
    if (VPL == 4) {
        float4 o; o.x = acc[0]; o.y = acc[1]; o.z = acc[2]; o.w = acc[3];
        *(float4*)op = o;
    } else {
        float2 o; o.x = acc[0]; o.y = acc[1];
        *(float2*)op = o;
    }
}

// ---------------------------------------------------------------------------
// Pooling + classifier
// ---------------------------------------------------------------------------
__global__ void pool_kernel(const int* __restrict__ batch, int n) {
    int t = blockIdx.x * blockDim.x + threadIdx.x;
    int node = t >> 4, lane = t & 15;
    if (node >= n) return;
    int g = batch[node];
    const float4 v = *(const float4*)&g_bufB[(size_t)node * 64 + lane * 4];
    float* o = &g_sums[g * 64 + lane * 4];
    atomicAdd(o + 0, v.x);
    atomicAdd(o + 1, v.y);
    atomicAdd(o + 2, v.z);
    atomicAdd(o + 3, v.w);
    if (lane == 0) atomicAdd(&g_cnt[g], 1.0f);
}

__global__ void final_kernel(const float* __restrict__ Wfc, const float* __restrict__ bfc,
                             float* __restrict__ out, int G) {
    int g = blockIdx.x * blockDim.x + threadIdx.x;
    if (g >= G) return;
    float c = fmaxf(g_cnt[g], 1.0f);
    float l0 = bfc[0], l1 = bfc[1];
    #pragma unroll
    for (int f = 0; f < 64; f++) {
        float p = g_sums[g * 64 + f] / c;
        l0 = fmaf(p, Wfc[f * 2 + 0], l0);
        l1 = fmaf(p, Wfc[f * 2 + 1], l1);
    }
    float m = fmaxf(l0, l1);
    float lse = m + logf(expf(l0 - m) + expf(l1 - m));
    out[2 * g + 0] = l0 - lse;
    out[2 * g + 1] = l1 - lse;
}

// ---------------------------------------------------------------------------
// Host launcher
// ---------------------------------------------------------------------------
extern "C" void kernel_launch(void* const* d_in, const int* in_sizes, int n_in,
                              void* d_out, int out_size) {
    const float* x    = (const float*)d_in[0];
    const int*   ei   = (const int*)d_in[1];
    const int*   bat  = (const int*)d_in[2];
    const float* W1   = (const float*)d_in[3];
    const float* b1   = (const float*)d_in[4];
    const float* W2   = (const float*)d_in[5];
    const float* as2  = (const float*)d_in[6];
    const float* ad2  = (const float*)d_in[7];
    const float* b2   = (const float*)d_in[8];
    const float* W3   = (const float*)d_in[9];
    const float* as3  = (const float*)d_in[10];
    const float* ad3  = (const float*)d_in[11];
    const float* b3   = (const float*)d_in[12];
    const float* Wfc  = (const float*)d_in[13];
    const float* bfc  = (const float*)d_in[14];

    const int n  = in_sizes[0] / 128;   // 50000
    const int E  = in_sizes[1] / 2;     // 800000
    const int G  = out_size / 2;        // 512
    const int* src = ei;
    const int* dst = ei + E;
    const int nb = (n + SCAN_CHUNK - 1) / SCAN_CHUNK;

    void *pBufA, *pBufB, *pDegi, *pSums, *pCnt;
    cudaGetSymbolAddress(&pBufA, g_bufA);
    cudaGetSymbolAddress(&pBufB, g_bufB);
    cudaGetSymbolAddress(&pDegi, g_degi);
    cudaGetSymbolAddress(&pSums, g_sums);
    cudaGetSymbolAddress(&pCnt,  g_cnt);

    const int TB = 256;
    auto cdiv = [](long long a, long long b) { return (int)((a + b - 1) / b); };

    // ===== CSR build (reused by all 3 layers) + layer-1 GEMM =====
    cudaMemsetAsync(pDegi, 0, (size_t)n * sizeof(int), 0);
    sgemm_kernel<0><<<dim3(1, cdiv(n, 64)), TB>>>(x, W1, (float*)pBufA, n, 64, 128, nullptr, nullptr);
    degi_kernel<<<cdiv(E, TB), TB>>>(dst, E);
    scan_reduce_kernel<<<nb, 512>>>(n);
    scan_boff_kernel<<<1, 32>>>(nb, n, E);
    scan_write_kernel<<<nb, 512>>>(n);
    csr_fill_kernel<<<cdiv(E, TB), TB>>>(src, dst, E);

    // ===== Layer 1: GCNConv(128 -> 64) + relu (fused) =====
    gcn_gather_kernel<<<cdiv((long long)n * 32, TB), TB>>>(b1, n);

    // ===== Layer 2: GATConv(64 -> 64, heads=2, concat) + relu =====
    sgemm_kernel<2><<<dim3(2, cdiv(n, 64)), TB>>>((const float*)pBufB, W2, (float*)pBufA, n, 128, 64, as2, ad2);
    gat_gather_kernel<2, 64, true><<<cdiv((long long)n * 32, TB), TB>>>(b2, n, (float*)pBufB);

    // ===== Layer 3: GATConv(128 -> 64, heads=1, mean) =====
    sgemm_kernel<1><<<dim3(1, cdiv(n, 64)), TB>>>((const float*)pBufB, W3, (float*)pBufA, n, 64, 128, as3, ad3);
    gat_gather_kernel<1, 64, false><<<cdiv((long long)n * 32, TB), TB>>>(b3, n, (float*)pBufB);

    // ===== Mean pool + FC + log_softmax =====
    cudaMemsetAsync(pSums, 0, (size_t)G * 64 * sizeof(float), 0);
    cudaMemsetAsync(pCnt,  0, (size_t)G * sizeof(float), 0);
    pool_kernel<<<cdiv((long long)n * 16, TB), TB>>>(bat, n);
    final_kernel<<<cdiv(G, TB), TB>>>(Wfc, bfc, (float*)d_out, G);
}

// round 8
// speedup vs baseline: 3.0582x; 1.0503x over previous
#include <cuda_runtime.h>
#include <cstdint>

// ---------------------------------------------------------------------------
// Problem constants (shapes fixed by the dataset)
// ---------------------------------------------------------------------------
#define MAXN 50048            // >= N=50000
#define MAXE 800000
#define MAXG 512
#define SCAN_CHUNK 4096       // elements per scan block (512 thr * 8)
#define MAXSB ((MAXN + SCAN_CHUNK - 1) / SCAN_CHUNK)

// ---------------------------------------------------------------------------
// Device scratch (static allocation — no cudaMalloc allowed)
// ---------------------------------------------------------------------------
__device__ __align__(16) float g_bufA[(size_t)MAXN * 128]; // GEMM outputs (transformed feats)
__device__ __align__(16) float g_bufB[(size_t)MAXN * 128]; // layer outputs
__device__ int   g_degi[MAXN];
__device__ int   g_rowptr[MAXN + 1];
__device__ int   g_cursor[MAXN];
__device__ int   g_col[MAXE];
__device__ int   g_bsum[MAXSB];
__device__ float g_dis[MAXN];
__device__ __align__(8) float g_als[MAXN * 2];
__device__ __align__(8) float g_ald[MAXN * 2];
__device__ __align__(16) float g_sums[MAXG * 64];
__device__ float g_cnt[MAXG];

// ---------------------------------------------------------------------------
// Tiled SGEMM: C[M,N] = A[M,K] @ B[K,N]. BM=128, BN=64, BK=16, 256 thr,
// 8x4 per thread. H > 0: fused GAT attention-logit epilogue (64-col block
// == one head; a_src/a_dst flattened index equals global output column).
// ---------------------------------------------------------------------------
template <int H>
__global__ void sgemm_kernel(const float* __restrict__ A, const float* __restrict__ B,
                             float* __restrict__ C, int M, int N, int K,
                             const float* __restrict__ a_src,
                             const float* __restrict__ a_dst) {
    __shared__ float As[16][132];  // transposed; 132*4=528 bytes (16B-mult stride)
    __shared__ float Bs[16][68];   // 68*4=272 bytes (16B-mult stride)
    const int bm = blockIdx.y * 128;
    const int bn = blockIdx.x * 64;
    const int tid = threadIdx.x;
    const int tx = tid & 15, ty = tid >> 4;   // 16 x 16 thread grid
    float acc[8][4] = {};
    for (int k0 = 0; k0 < K; k0 += 16) {
        // A tile: 128 rows x 16 k, 2 float4 loads / thread, scalar transposed stores
        {
            int r = tid >> 1, c8 = (tid & 1) * 8;
            int row = bm + r;
            float4 v0 = make_float4(0.f, 0.f, 0.f, 0.f);
            float4 v1 = make_float4(0.f, 0.f, 0.f, 0.f);
            if (row < M) {
                v0 = *(const float4*)&A[(size_t)row * K + k0 + c8];
                v1 = *(const float4*)&A[(size_t)row * K + k0 + c8 + 4];
            }
            As[c8 + 0][r] = v0.x; As[c8 + 1][r] = v0.y;
            As[c8 + 2][r] = v0.z; As[c8 + 3][r] = v0.w;
            As[c8 + 4][r] = v1.x; As[c8 + 5][r] = v1.y;
            As[c8 + 6][r] = v1.z; As[c8 + 7][r] = v1.w;
        }
        // B tile: 16 k x 64 cols, float4 loads + float4 smem stores
        {
            int r = tid >> 4, c4 = (tid & 15) * 4;
            float4 v = *(const float4*)&B[(size_t)(k0 + r) * N + bn + c4];
            *(float4*)&Bs[r][c4] = v;
        }
        __syncthreads();
        #pragma unroll
        for (int k = 0; k < 16; k++) {
            float4 a0 = *(const float4*)&As[k][ty * 8];
            float4 a1 = *(const float4*)&As[k][ty * 8 + 4];
            float4 b0 = *(const float4*)&Bs[k][tx * 4];
            float a[8] = {a0.x, a0.y, a0.z, a0.w, a1.x, a1.y, a1.z, a1.w};
            float b[4] = {b0.x, b0.y, b0.z, b0.w};
            #pragma unroll
            for (int i = 0; i < 8; i++)
                #pragma unroll
                for (int j = 0; j < 4; j++)
                    acc[i][j] = fmaf(a[i], b[j], acc[i][j]);
        }
        __syncthreads();
    }
    #pragma unroll
    for (int i = 0; i < 8; i++) {
        int row = bm + ty * 8 + i;
        if (row < M) {
            float4 o;
            o.x = acc[i][0]; o.y = acc[i][1]; o.z = acc[i][2]; o.w = acc[i][3];
            *(float4*)&C[(size_t)row * N + bn + tx * 4] = o;
        }
    }
    if (H > 0) {
        // attention logits: per-row dot of this head's 64 cols with a_src/a_dst
        const int hd = bn >> 6;
        float asr[4], adr[4];
        #pragma unroll
        for (int j = 0; j < 4; j++) {
            asr[j] = a_src[bn + tx * 4 + j];
            adr[j] = a_dst[bn + tx * 4 + j];
        }
        #pragma unroll
        for (int i = 0; i < 8; i++) {
            float s = 0.f, d = 0.f;
            #pragma unroll
            for (int j = 0; j < 4; j++) {
                s = fmaf(acc[i][j], asr[j], s);
                d = fmaf(acc[i][j], adr[j], d);
            }
            // reduce across the 16 tx lanes (xor offsets < 16 stay in-group)
            #pragma unroll
            for (int off = 8; off >= 1; off >>= 1) {
                s += __shfl_xor_sync(0xffffffffu, s, off);
                d += __shfl_xor_sync(0xffffffffu, d, off);
            }
            int row = bm + ty * 8 + i;
            if (tx == 0 && row < M) {
                g_als[row * H + hd] = s;
                g_ald[row * H + hd] = d;
            }
        }
    }
}

// ---------------------------------------------------------------------------
// CSR build (dst-indexed, real edges only; self-loops handled inline later)
// ---------------------------------------------------------------------------
__global__ void degi_kernel(const int* __restrict__ dst, int E) {
    int i = blockIdx.x * blockDim.x + threadIdx.x;
    if (i < E) atomicAdd(&g_degi[dst[i]], 1);
}

__global__ void scan_reduce_kernel(int n) {
    __shared__ int red[512];
    const int b = blockIdx.x, t = threadIdx.x;
    const int base = b * SCAN_CHUNK;
    int s = 0;
    #pragma unroll
    for (int i = t; i < SCAN_CHUNK; i += 512) {
        int idx = base + i;
        if (idx < n) s += g_degi[idx];
    }
    red[t] = s;
    __syncthreads();
    #pragma unroll
    for (int off = 256; off > 0; off >>= 1) {
        if (t < off) red[t] += red[t + off];
        __syncthreads();
    }
    if (t == 0) g_bsum[b] = red[0];
}

// per-block scan + write rowptr/cursor/dis; block offset computed inline
__global__ void scan_write_kernel(int n) {
    __shared__ int sm[512];
    const int b = blockIdx.x, t = threadIdx.x;
    const int start = b * SCAN_CHUNK + t * 8;
    int vals[8];
    int s = 0;
    #pragma unroll
    for (int i = 0; i < 8; i++) {
        int idx = start + i;
        vals[i] = (idx < n) ? g_degi[idx] : 0;
        s += vals[i];
    }
    sm[t] = s;
    __syncthreads();
    #pragma unroll
    for (int off = 1; off < 512; off <<= 1) {
        int v = (t >= off) ? sm[t - off] : 0;
        __syncthreads();
        sm[t] += v;
        __syncthreads();
    }
    // block offset: sum of preceding block sums (nb <= 13, trivial)
    int boff = 0;
    for (int i = 0; i < b; i++) boff += g_bsum[i];
    int excl = boff + ((t == 0) ? 0 : sm[t - 1]);
    #pragma unroll
    for (int i = 0; i < 8; i++) {
        int idx = start + i;
        if (idx < n) {
            g_rowptr[idx] = excl;
            g_cursor[idx] = excl;
            g_dis[idx] = rsqrtf((float)(vals[i] + 1));  // +1 self-loop
            excl += vals[i];
            if (idx == n - 1) g_rowptr[n] = excl;
        }
    }
}

__global__ void csr_fill_kernel(const int* __restrict__ src,
                                const int* __restrict__ dst, int E) {
    int e = blockIdx.x * blockDim.x + threadIdx.x;
    if (e >= E) return;
    int pos = atomicAdd(&g_cursor[dst[e]], 1);
    g_col[pos] = src[e];
}

// ---------------------------------------------------------------------------
// GCN aggregation: warp per node, warp-staged edges, 4-unrolled inner loop.
// ---------------------------------------------------------------------------
__global__ void gcn_gather_kernel(const float* __restrict__ b1, int n) {
    __shared__ int   s_col[8][32];
    __shared__ float s_wt[8][32];
    const int w = (blockIdx.x * blockDim.x + threadIdx.x) >> 5;
    const int lane = threadIdx.x & 31;
    const int wrp = threadIdx.x >> 5;
    if (w >= n) return;
    const int d = w;
    const float dd = g_dis[d];
    const float2 sv = *(const float2*)&g_bufA[(size_t)d * 64 + lane * 2];
    float ax = dd * dd * sv.x;
    float ay = dd * dd * sv.y;
    const int beg = g_rowptr[d], end = g_rowptr[d + 1];

    auto proc = [&](int k) {
        int s = s_col[wrp][k];
        float ws = s_wt[wrp][k];
        const float2 v = *(const float2*)&g_bufA[(size_t)s * 64 + lane * 2];
        ax = fmaf(ws, v.x, ax);
        ay = fmaf(ws, v.y, ay);
    };

    for (int j0 = beg; j0 < end; j0 += 32) {
        const int cnt = min(32, end - j0);
        if (lane < cnt) {
            int s = g_col[j0 + lane];
            s_col[wrp][lane] = s;
            s_wt[wrp][lane] = g_dis[s] * dd;
        }
        __syncwarp();
        int k = 0;
        for (; k + 4 <= cnt; k += 4) { proc(k); proc(k + 1); proc(k + 2); proc(k + 3); }
        for (; k < cnt; k++) proc(k);
        __syncwarp();
    }
    ax += b1[lane * 2];
    ay += b1[lane * 2 + 1];
    float2 o;
    o.x = ax > 0.0f ? ax : 0.0f;
    o.y = ay > 0.0f ? ay : 0.0f;
    *(float2*)&g_bufB[(size_t)d * 64 + lane * 2] = o;
}

// ---------------------------------------------------------------------------
// GAT aggregation: warp per node, warp-staged edges, chunk-max online softmax.
// ---------------------------------------------------------------------------
template <int H, int F, bool RELU>
__global__ void gat_gather_kernel(const float* __restrict__ bias, int n,
                                  float* __restrict__ out) {
    constexpr int HF = H * F;
    constexpr int VPL = HF / 32;          // values per lane (2 or 4)
    __shared__ int   s_col[8][32];
    __shared__ float s_e[8][H * 32];      // leaky-relu'd logits per head
    const int w = (blockIdx.x * blockDim.x + threadIdx.x) >> 5;
    const int lane = threadIdx.x & 31;
    const int wrp = threadIdx.x >> 5;
    if (w >= n) return;
    const int d = w;
    const int hd = (lane * VPL) / F;      // this lane's head

    float ald_d[H], m[H], l[H];
    #pragma unroll
    for (int h = 0; h < H; h++) {
        ald_d[h] = g_ald[d * H + h];
        float v = g_als[d * H + h] + ald_d[h];
        v = v > 0.0f ? v : 0.2f * v;      // leaky relu
        m[h] = v;
        l[h] = 1.0f;
    }

    // self-loop contribution (exp(v - m) = 1 at init)
    float acc[VPL];
    {
        const float* sp = &g_bufA[(size_t)d * HF + lane * VPL];
        if (VPL == 4) {
            const float4 v = *(const float4*)sp;
            acc[0] = v.x; acc[1] = v.y; acc[2] = v.z; acc[3] = v.w;
        } else {
            const float2 v = *(const float2*)sp;
            acc[0] = v.x; acc[1] = v.y;
        }
    }

    const int beg = g_rowptr[d], end = g_rowptr[d + 1];

    auto proc = [&](int k) {
        int s = s_col[wrp][k];
        float ex[H];
        #pragma unroll
        for (int h = 0; h < H; h++) {
            ex[h] = __expf(s_e[wrp][h * 32 + k] - m[h]);
            l[h] += ex[h];
        }
        float ee = (H == 2 && hd == 1) ? ex[1] : ex[0];
        const float* sp = &g_bufA[(size_t)s * HF + lane * VPL];
        if (VPL == 4) {
            const float4 v = *(const float4*)sp;
            acc[0] = fmaf(ee, v.x, acc[0]);
            acc[1] = fmaf(ee, v.y, acc[1]);
            acc[2] = fmaf(ee, v.z, acc[2]);
            acc[3] = fmaf(ee, v.w, acc[3]);
        } else {
            const float2 v = *(const float2*)sp;
            acc[0] = fmaf(ee, v.x, acc[0]);
            acc[1] = fmaf(ee, v.y, acc[1]);
        }
    };

    for (int j0 = beg; j0 < end; j0 += 32) {
        const int cnt = min(32, end - j0);
        float myv[H];
        #pragma unroll
        for (int h = 0; h < H; h++) myv[h] = -3.0e38f;
        if (lane < cnt) {
            int s = g_col[j0 + lane];
            s_col[wrp][lane] = s;
            #pragma unroll
            for (int h = 0; h < H; h++) {
                float v = g_als[s * H + h] + ald_d[h];
                v = v > 0.0f ? v : 0.2f * v;
                s_e[wrp][h * 32 + lane] = v;
                myv[h] = v;
            }
        }
        // chunk max per head + single rescale
        #pragma unroll
        for (int h = 0; h < H; h++) {
            float cm = myv[h];
            #pragma unroll
            for (int off = 16; off >= 1; off >>= 1)
                cm = fmaxf(cm, __shfl_xor_sync(0xffffffffu, cm, off));
            if (cm > m[h]) {
                float r = __expf(m[h] - cm);
                l[h] *= r;
                if (h == ((H == 2) ? hd : 0)) {
                    #pragma unroll
                    for (int i = 0; i < VPL; i++) acc[i] *= r;
                }
                m[h] = cm;
            }
        }
        __syncwarp();
        int k = 0;
        for (; k + 4 <= cnt; k += 4) { proc(k); proc(k + 1); proc(k + 2); proc(k + 3); }
        for (; k < cnt; k++) proc(k);
        __syncwarp();
    }

    const float inv = 1.0f / ((H == 2 && hd == 1) ? l[1] : l[0]);
    #pragma unroll
    for (int i = 0; i < VPL; i++) {
        float v = acc[i] * inv + bias[lane * VPL + i];
        if (RELU) v = v > 0.0f ? v : 0.0f;
        acc[i] = v;
    }
    float* op = &out[(size_t)d * HF + lane * VPL];
    if (VPL == 4) {
        float4 o; o.x = acc[0]; o.y = acc[1]; o.z = acc[2]; o.w = acc[3];
        *(float4*)op = o;
    } else {
        float2 o; o.x = acc[0]; o.y = acc[1];
        *(float2*)op = o;
    }
}

// ---------------------------------------------------------------------------
// Pooling + classifier
// ---------------------------------------------------------------------------
__global__ void pool_kernel(const int* __restrict__ batch, int n) {
    int t = blockIdx.x * blockDim.x + threadIdx.x;
    int node = t >> 4, lane = t & 15;
    if (node >= n) return;
    int g = batch[node];
    const float4 v = *(const float4*)&g_bufB[(size_t)node * 64 + lane * 4];
    float* o = &g_sums[g * 64 + lane * 4];
    atomicAdd(o + 0, v.x);
    atomicAdd(o + 1, v.y);
    atomicAdd(o + 2, v.z);
    atomicAdd(o + 3, v.w);
    if (lane == 0) atomicAdd(&g_cnt[g], 1.0f);
}

__global__ void final_kernel(const float* __restrict__ Wfc, const float* __restrict__ bfc,
                             float* __restrict__ out, int G) {
    int g = blockIdx.x * blockDim.x + threadIdx.x;
    if (g >= G) return;
    float c = fmaxf(g_cnt[g], 1.0f);
    float l0 = bfc[0], l1 = bfc[1];
    #pragma unroll
    for (int f = 0; f < 64; f++) {
        float p = g_sums[g * 64 + f] / c;
        l0 = fmaf(p, Wfc[f * 2 + 0], l0);
        l1 = fmaf(p, Wfc[f * 2 + 1], l1);
    }
    float m = fmaxf(l0, l1);
    float lse = m + logf(expf(l0 - m) + expf(l1 - m));
    out[2 * g + 0] = l0 - lse;
    out[2 * g + 1] = l1 - lse;
}

// ---------------------------------------------------------------------------
// Host launcher
// ---------------------------------------------------------------------------
extern "C" void kernel_launch(void* const* d_in, const int* in_sizes, int n_in,
                              void* d_out, int out_size) {
    const float* x    = (const float*)d_in[0];
    const int*   ei   = (const int*)d_in[1];
    const int*   bat  = (const int*)d_in[2];
    const float* W1   = (const float*)d_in[3];
    const float* b1   = (const float*)d_in[4];
    const float* W2   = (const float*)d_in[5];
    const float* as2  = (const float*)d_in[6];
    const float* ad2  = (const float*)d_in[7];
    const float* b2   = (const float*)d_in[8];
    const float* W3   = (const float*)d_in[9];
    const float* as3  = (const float*)d_in[10];
    const float* ad3  = (const float*)d_in[11];
    const float* b3   = (const float*)d_in[12];
    const float* Wfc  = (const float*)d_in[13];
    const float* bfc  = (const float*)d_in[14];

    const int n  = in_sizes[0] / 128;   // 50000
    const int E  = in_sizes[1] / 2;     // 800000
    const int G  = out_size / 2;        // 512
    const int* src = ei;
    const int* dst = ei + E;
    const int nb = (n + SCAN_CHUNK - 1) / SCAN_CHUNK;

    void *pBufA, *pBufB, *pDegi, *pSums, *pCnt;
    cudaGetSymbolAddress(&pBufA, g_bufA);
    cudaGetSymbolAddress(&pBufB, g_bufB);
    cudaGetSymbolAddress(&pDegi, g_degi);
    cudaGetSymbolAddress(&pSums, g_sums);
    cudaGetSymbolAddress(&pCnt,  g_cnt);

    const int TB = 256;
    auto cdiv = [](long long a, long long b) { return (int)((a + b - 1) / b); };

    // ===== CSR build (reused by all 3 layers) + layer-1 GEMM =====
    cudaMemsetAsync(pDegi, 0, (size_t)n * sizeof(int), 0);
    sgemm_kernel<0><<<dim3(1, cdiv(n, 128)), TB>>>(x, W1, (float*)pBufA, n, 64, 128, nullptr, nullptr);
    degi_kernel<<<cdiv(E, TB), TB>>>(dst, E);
    scan_reduce_kernel<<<nb, 512>>>(n);
    scan_write_kernel<<<nb, 512>>>(n);
    csr_fill_kernel<<<cdiv(E, TB), TB>>>(src, dst, E);

    // ===== Layer 1: GCNConv(128 -> 64) + relu (fused) =====
    gcn_gather_kernel<<<cdiv((long long)n * 32, TB), TB>>>(b1, n);

    // ===== Layer 2: GATConv(64 -> 64, heads=2, concat) + relu =====
    sgemm_kernel<2><<<dim3(2, cdiv(n, 128)), TB>>>((const float*)pBufB, W2, (float*)pBufA, n, 128, 64, as2, ad2);
    gat_gather_kernel<2, 64, true><<<cdiv((long long)n * 32, TB), TB>>>(b2, n, (float*)pBufB);

    // ===== Layer 3: GATConv(128 -> 64, heads=1, mean) =====
    sgemm_kernel<1><<<dim3(1, cdiv(n, 128)), TB>>>((const float*)pBufB, W3, (float*)pBufA, n, 64, 128, as3, ad3);
    gat_gather_kernel<1, 64, false><<<cdiv((long long)n * 32, TB), TB>>>(b3, n, (float*)pBufB);

    // ===== Mean pool + FC + log_softmax =====
    cudaMemsetAsync(pSums, 0, (size_t)G * 64 * sizeof(float), 0);
    cudaMemsetAsync(pCnt,  0, (size_t)G * sizeof(float), 0);
    pool_kernel<<<cdiv((long long)n * 16, TB), TB>>>(bat, n);
    final_kernel<<<cdiv(G, TB), TB>>>(Wfc, bfc, (float*)d_out, G);
}

// round 9
// speedup vs baseline: 3.2561x; 1.0647x over previous
#include <cuda_runtime.h>
#include <cstdint>

// ---------------------------------------------------------------------------
// Problem constants (shapes fixed by the dataset)
// ---------------------------------------------------------------------------
#define MAXN 50048            // >= N=50000
#define MAXE 800000
#define MAXG 512
#define SCAN_CHUNK 4096       // elements per scan block (512 thr * 8)
#define MAXSB ((MAXN + SCAN_CHUNK - 1) / SCAN_CHUNK)

// ---------------------------------------------------------------------------
// Device scratch (static allocation — no cudaMalloc allowed)
// ---------------------------------------------------------------------------
__device__ __align__(16) float g_bufA[(size_t)MAXN * 128]; // GEMM outputs (transformed feats)
__device__ __align__(16) float g_bufB[(size_t)MAXN * 128]; // layer outputs
__device__ int   g_degi[MAXN];
__device__ int   g_rowptr[MAXN + 1];
__device__ int   g_cursor[MAXN];
__device__ int   g_col[MAXE];
__device__ int   g_bsum[MAXSB];
__device__ float g_dis[MAXN];
__device__ __align__(8) float g_als[MAXN * 2];
__device__ __align__(8) float g_ald[MAXN * 2];
__device__ __align__(16) float g_sums[MAXG * 64];
__device__ float g_cnt[MAXG];

// ---------------------------------------------------------------------------
// Side stream + events for fork/join inside graph capture (created once at
// process init; kernel_launch itself performs identical work every call).
// ---------------------------------------------------------------------------
struct SideStream {
    cudaStream_t s;
    cudaEvent_t fork, join;
    SideStream() {
        cudaStreamCreateWithFlags(&s, cudaStreamNonBlocking);
        cudaEventCreateWithFlags(&fork, cudaEventDisableTiming);
        cudaEventCreateWithFlags(&join, cudaEventDisableTiming);
    }
};
static SideStream g_side;

// ---------------------------------------------------------------------------
// Tiled SGEMM: C[M,N] = A[M,K] @ B[K,N]. BM=128, BN=64, BK=16, 256 thr,
// 8x4 per thread. H > 0: fused GAT attention-logit epilogue (64-col block
// == one head; a_src/a_dst flattened index equals global output column).
// ---------------------------------------------------------------------------
template <int H>
__global__ void sgemm_kernel(const float* __restrict__ A, const float* __restrict__ B,
                             float* __restrict__ C, int M, int N, int K,
                             const float* __restrict__ a_src,
                             const float* __restrict__ a_dst) {
    __shared__ float As[16][132];  // transposed; 132*4=528 bytes (16B-mult stride)
    __shared__ float Bs[16][68];   // 68*4=272 bytes (16B-mult stride)
    const int bm = blockIdx.y * 128;
    const int bn = blockIdx.x * 64;
    const int tid = threadIdx.x;
    const int tx = tid & 15, ty = tid >> 4;   // 16 x 16 thread grid
    float acc[8][4] = {};
    for (int k0 = 0; k0 < K; k0 += 16) {
        // A tile: 128 rows x 16 k, 2 float4 loads / thread, scalar transposed stores
        {
            int r = tid >> 1, c8 = (tid & 1) * 8;
            int row = bm + r;
            float4 v0 = make_float4(0.f, 0.f, 0.f, 0.f);
            float4 v1 = make_float4(0.f, 0.f, 0.f, 0.f);
            if (row < M) {
                v0 = *(const float4*)&A[(size_t)row * K + k0 + c8];
                v1 = *(const float4*)&A[(size_t)row * K + k0 + c8 + 4];
            }
            As[c8 + 0][r] = v0.x; As[c8 + 1][r] = v0.y;
            As[c8 + 2][r] = v0.z; As[c8 + 3][r] = v0.w;
            As[c8 + 4][r] = v1.x; As[c8 + 5][r] = v1.y;
            As[c8 + 6][r] = v1.z; As[c8 + 7][r] = v1.w;
        }
        // B tile: 16 k x 64 cols, float4 loads + float4 smem stores
        {
            int r = tid >> 4, c4 = (tid & 15) * 4;
            float4 v = *(const float4*)&B[(size_t)(k0 + r) * N + bn + c4];
            *(float4*)&Bs[r][c4] = v;
        }
        __syncthreads();
        #pragma unroll
        for (int k = 0; k < 16; k++) {
            float4 a0 = *(const float4*)&As[k][ty * 8];
            float4 a1 = *(const float4*)&As[k][ty * 8 + 4];
            float4 b0 = *(const float4*)&Bs[k][tx * 4];
            float a[8] = {a0.x, a0.y, a0.z, a0.w, a1.x, a1.y, a1.z, a1.w};
            float b[4] = {b0.x, b0.y, b0.z, b0.w};
            #pragma unroll
            for (int i = 0; i < 8; i++)
                #pragma unroll
                for (int j = 0; j < 4; j++)
                    acc[i][j] = fmaf(a[i], b[j], acc[i][j]);
        }
        __syncthreads();
    }
    #pragma unroll
    for (int i = 0; i < 8; i++) {
        int row = bm + ty * 8 + i;
        if (row < M) {
            float4 o;
            o.x = acc[i][0]; o.y = acc[i][1]; o.z = acc[i][2]; o.w = acc[i][3];
            *(float4*)&C[(size_t)row * N + bn + tx * 4] = o;
        }
    }
    if (H > 0) {
        // attention logits: per-row dot of this head's 64 cols with a_src/a_dst
        const int hd = bn >> 6;
        float asr[4], adr[4];
        #pragma unroll
        for (int j = 0; j < 4; j++) {
            asr[j] = a_src[bn + tx * 4 + j];
            adr[j] = a_dst[bn + tx * 4 + j];
        }
        #pragma unroll
        for (int i = 0; i < 8; i++) {
            float s = 0.f, d = 0.f;
            #pragma unroll
            for (int j = 0; j < 4; j++) {
                s = fmaf(acc[i][j], asr[j], s);
                d = fmaf(acc[i][j], adr[j], d);
            }
            // reduce across the 16 tx lanes (xor offsets < 16 stay in-group)
            #pragma unroll
            for (int off = 8; off >= 1; off >>= 1) {
                s += __shfl_xor_sync(0xffffffffu, s, off);
                d += __shfl_xor_sync(0xffffffffu, d, off);
            }
            int row = bm + ty * 8 + i;
            if (tx == 0 && row < M) {
                g_als[row * H + hd] = s;
                g_ald[row * H + hd] = d;
            }
        }
    }
}

// ---------------------------------------------------------------------------
// CSR build (dst-indexed, real edges only; self-loops handled inline later)
// ---------------------------------------------------------------------------
__global__ void degi_kernel(const int* __restrict__ dst, int E) {
    int i = blockIdx.x * blockDim.x + threadIdx.x;
    if (i < E) atomicAdd(&g_degi[dst[i]], 1);
}

__global__ void scan_reduce_kernel(int n) {
    __shared__ int red[512];
    const int b = blockIdx.x, t = threadIdx.x;
    const int base = b * SCAN_CHUNK;
    int s = 0;
    #pragma unroll
    for (int i = t; i < SCAN_CHUNK; i += 512) {
        int idx = base + i;
        if (idx < n) s += g_degi[idx];
    }
    red[t] = s;
    __syncthreads();
    #pragma unroll
    for (int off = 256; off > 0; off >>= 1) {
        if (t < off) red[t] += red[t + off];
        __syncthreads();
    }
    if (t == 0) g_bsum[b] = red[0];
}

// per-block scan via warp shuffles (2 barriers); block offset inline (nb<=13)
__global__ void scan_write_kernel(int n) {
    __shared__ int wsum[16];
    const int b = blockIdx.x, t = threadIdx.x;
    const int lane = t & 31, wid = t >> 5;
    const int start = b * SCAN_CHUNK + t * 8;
    int vals[8];
    int s = 0;
    #pragma unroll
    for (int i = 0; i < 8; i++) {
        int idx = start + i;
        vals[i] = (idx < n) ? g_degi[idx] : 0;
        s += vals[i];
    }
    // warp inclusive scan of per-thread sums
    int ps = s;
    #pragma unroll
    for (int off = 1; off < 32; off <<= 1) {
        int v = __shfl_up_sync(0xffffffffu, ps, off);
        if (lane >= off) ps += v;
    }
    if (lane == 31) wsum[wid] = ps;
    __syncthreads();
    if (wid == 0 && lane < 16) {
        int v = wsum[lane];
        #pragma unroll
        for (int off = 1; off < 16; off <<= 1) {
            int u = __shfl_up_sync(0x0000ffffu, v, off);
            if (lane >= off) v += u;
        }
        wsum[lane] = v;   // inclusive warp-sums
    }
    __syncthreads();
    int boff = 0;
    for (int i = 0; i < b; i++) boff += g_bsum[i];
    int excl = boff + ((wid > 0) ? wsum[wid - 1] : 0) + (ps - s);
    #pragma unroll
    for (int i = 0; i < 8; i++) {
        int idx = start + i;
        if (idx < n) {
            g_rowptr[idx] = excl;
            g_cursor[idx] = excl;
            g_dis[idx] = rsqrtf((float)(vals[i] + 1));  // +1 self-loop
            excl += vals[i];
            if (idx == n - 1) g_rowptr[n] = excl;
        }
    }
}

__global__ void csr_fill_kernel(const int* __restrict__ src,
                                const int* __restrict__ dst, int E) {
    int e = blockIdx.x * blockDim.x + threadIdx.x;
    if (e >= E) return;
    int pos = atomicAdd(&g_cursor[dst[e]], 1);
    g_col[pos] = src[e];
}

// ---------------------------------------------------------------------------
// GCN aggregation: warp per node, warp-staged edges, 4-unrolled inner loop.
// ---------------------------------------------------------------------------
__global__ void gcn_gather_kernel(const float* __restrict__ b1, int n) {
    __shared__ int   s_col[8][32];
    __shared__ float s_wt[8][32];
    const int w = (blockIdx.x * blockDim.x + threadIdx.x) >> 5;
    const int lane = threadIdx.x & 31;
    const int wrp = threadIdx.x >> 5;
    if (w >= n) return;
    const int d = w;
    const float dd = g_dis[d];
    const float2 sv = *(const float2*)&g_bufA[(size_t)d * 64 + lane * 2];
    float ax = dd * dd * sv.x;
    float ay = dd * dd * sv.y;
    const int beg = g_rowptr[d], end = g_rowptr[d + 1];

    auto proc = [&](int k) {
        int s = s_col[wrp][k];
        float ws = s_wt[wrp][k];
        const float2 v = *(const float2*)&g_bufA[(size_t)s * 64 + lane * 2];
        ax = fmaf(ws, v.x, ax);
        ay = fmaf(ws, v.y, ay);
    };

    for (int j0 = beg; j0 < end; j0 += 32) {
        const int cnt = min(32, end - j0);
        if (lane < cnt) {
            int s = g_col[j0 + lane];
            s_col[wrp][lane] = s;
            s_wt[wrp][lane] = g_dis[s] * dd;
        }
        __syncwarp();
        int k = 0;
        for (; k + 4 <= cnt; k += 4) { proc(k); proc(k + 1); proc(k + 2); proc(k + 3); }
        for (; k < cnt; k++) proc(k);
        __syncwarp();
    }
    ax += b1[lane * 2];
    ay += b1[lane * 2 + 1];
    float2 o;
    o.x = ax > 0.0f ? ax : 0.0f;
    o.y = ay > 0.0f ? ay : 0.0f;
    *(float2*)&g_bufB[(size_t)d * 64 + lane * 2] = o;
}

// ---------------------------------------------------------------------------
// GAT aggregation: warp per node, warp-staged edges, chunk-max online softmax.
// ---------------------------------------------------------------------------
template <int H, int F, bool RELU>
__global__ void gat_gather_kernel(const float* __restrict__ bias, int n,
                                  float* __restrict__ out) {
    constexpr int HF = H * F;
    constexpr int VPL = HF / 32;          // values per lane (2 or 4)
    __shared__ int   s_col[8][32];
    __shared__ float s_e[8][H * 32];      // leaky-relu'd logits per head
    const int w = (blockIdx.x * blockDim.x + threadIdx.x) >> 5;
    const int lane = threadIdx.x & 31;
    const int wrp = threadIdx.x >> 5;
    if (w >= n) return;
    const int d = w;
    const int hd = (lane * VPL) / F;      // this lane's head

    float ald_d[H], m[H], l[H];
    #pragma unroll
    for (int h = 0; h < H; h++) {
        ald_d[h] = g_ald[d * H + h];
        float v = g_als[d * H + h] + ald_d[h];
        v = v > 0.0f ? v : 0.2f * v;      // leaky relu
        m[h] = v;
        l[h] = 1.0f;
    }

    // self-loop contribution (exp(v - m) = 1 at init)
    float acc[VPL];
    {
        const float* sp = &g_bufA[(size_t)d * HF + lane * VPL];
        if (VPL == 4) {
            const float4 v = *(const float4*)sp;
            acc[0] = v.x; acc[1] = v.y; acc[2] = v.z; acc[3] = v.w;
        } else {
            const float2 v = *(const float2*)sp;
            acc[0] = v.x; acc[1] = v.y;
        }
    }

    const int beg = g_rowptr[d], end = g_rowptr[d + 1];

    auto proc = [&](int k) {
        int s = s_col[wrp][k];
        float ex[H];
        #pragma unroll
        for (int h = 0; h < H; h++) {
            ex[h] = __expf(s_e[wrp][h * 32 + k] - m[h]);
            l[h] += ex[h];
        }
        float ee = (H == 2 && hd == 1) ? ex[1] : ex[0];
        const float* sp = &g_bufA[(size_t)s * HF + lane * VPL];
        if (VPL == 4) {
            const float4 v = *(const float4*)sp;
            acc[0] = fmaf(ee, v.x, acc[0]);
            acc[1] = fmaf(ee, v.y, acc[1]);
            acc[2] = fmaf(ee, v.z, acc[2]);
            acc[3] = fmaf(ee, v.w, acc[3]);
        } else {
            const float2 v = *(const float2*)sp;
            acc[0] = fmaf(ee, v.x, acc[0]);
            acc[1] = fmaf(ee, v.y, acc[1]);
        }
    };

    for (int j0 = beg; j0 < end; j0 += 32) {
        const int cnt = min(32, end - j0);
        float myv[H];
        #pragma unroll
        for (int h = 0; h < H; h++) myv[h] = -3.0e38f;
        if (lane < cnt) {
            int s = g_col[j0 + lane];
            s_col[wrp][lane] = s;
            #pragma unroll
            for (int h = 0; h < H; h++) {
                float v = g_als[s * H + h] + ald_d[h];
                v = v > 0.0f ? v : 0.2f * v;
                s_e[wrp][h * 32 + lane] = v;
                myv[h] = v;
            }
        }
        // chunk max per head + single rescale
        #pragma unroll
        for (int h = 0; h < H; h++) {
            float cm = myv[h];
            #pragma unroll
            for (int off = 16; off >= 1; off >>= 1)
                cm = fmaxf(cm, __shfl_xor_sync(0xffffffffu, cm, off));
            if (cm > m[h]) {
                float r = __expf(m[h] - cm);
                l[h] *= r;
                if (h == ((H == 2) ? hd : 0)) {
                    #pragma unroll
                    for (int i = 0; i < VPL; i++) acc[i] *= r;
                }
                m[h] = cm;
            }
        }
        __syncwarp();
        int k = 0;
        for (; k + 4 <= cnt; k += 4) { proc(k); proc(k + 1); proc(k + 2); proc(k + 3); }
        for (; k < cnt; k++) proc(k);
        __syncwarp();
    }

    const float inv = 1.0f / ((H == 2 && hd == 1) ? l[1] : l[0]);
    #pragma unroll
    for (int i = 0; i < VPL; i++) {
        float v = acc[i] * inv + bias[lane * VPL + i];
        if (RELU) v = v > 0.0f ? v : 0.0f;
        acc[i] = v;
    }
    float* op = &out[(size_t)d * HF + lane * VPL];
    if (VPL == 4) {
        float4 o; o.x = acc[0]; o.y = acc[1]; o.z = acc[2]; o.w = acc[3];
        *(float4*)op = o;
    } else {
        float2 o; o.x = acc[0]; o.y = acc[1];
        *(float2*)op = o;
    }
}

// ---------------------------------------------------------------------------
// Pooling + classifier
// ---------------------------------------------------------------------------
__global__ void pool_kernel(const int* __restrict__ batch, int n) {
    int t = blockIdx.x * blockDim.x + threadIdx.x;
    int node = t >> 4, lane = t & 15;
    if (node >= n) return;
    int g = batch[node];
    const float4 v = *(const float4*)&g_bufB[(size_t)node * 64 + lane * 4];
    float* o = &g_sums[g * 64 + lane * 4];
    atomicAdd(o + 0, v.x);
    atomicAdd(o + 1, v.y);
    atomicAdd(o + 2, v.z);
    atomicAdd(o + 3, v.w);
    if (lane == 0) atomicAdd(&g_cnt[g], 1.0f);
}

__global__ void final_kernel(const float* __restrict__ Wfc, const float* __restrict__ bfc,
                             float* __restrict__ out, int G) {
    int g = blockIdx.x * blockDim.x + threadIdx.x;
    if (g >= G) return;
    float c = fmaxf(g_cnt[g], 1.0f);
    float l0 = bfc[0], l1 = bfc[1];
    #pragma unroll
    for (int f = 0; f < 64; f++) {
        float p = g_sums[g * 64 + f] / c;
        l0 = fmaf(p, Wfc[f * 2 + 0], l0);
        l1 = fmaf(p, Wfc[f * 2 + 1], l1);
    }
    float m = fmaxf(l0, l1);
    float lse = m + logf(expf(l0 - m) + expf(l1 - m));
    out[2 * g + 0] = l0 - lse;
    out[2 * g + 1] = l1 - lse;
}

// ---------------------------------------------------------------------------
// Host launcher
// ---------------------------------------------------------------------------
extern "C" void kernel_launch(void* const* d_in, const int* in_sizes, int n_in,
                              void* d_out, int out_size) {
    const float* x    = (const float*)d_in[0];
    const int*   ei   = (const int*)d_in[1];
    const int*   bat  = (const int*)d_in[2];
    const float* W1   = (const float*)d_in[3];
    const float* b1   = (const float*)d_in[4];
    const float* W2   = (const float*)d_in[5];
    const float* as2  = (const float*)d_in[6];
    const float* ad2  = (const float*)d_in[7];
    const float* b2   = (const float*)d_in[8];
    const float* W3   = (const float*)d_in[9];
    const float* as3  = (const float*)d_in[10];
    const float* ad3  = (const float*)d_in[11];
    const float* b3   = (const float*)d_in[12];
    const float* Wfc  = (const float*)d_in[13];
    const float* bfc  = (const float*)d_in[14];

    const int n  = in_sizes[0] / 128;   // 50000
    const int E  = in_sizes[1] / 2;     // 800000
    const int G  = out_size / 2;        // 512
    const int* src = ei;
    const int* dst = ei + E;
    const int nb = (n + SCAN_CHUNK - 1) / SCAN_CHUNK;

    void *pBufA, *pBufB, *pDegi, *pSums, *pCnt;
    cudaGetSymbolAddress(&pBufA, g_bufA);
    cudaGetSymbolAddress(&pBufB, g_bufB);
    cudaGetSymbolAddress(&pDegi, g_degi);
    cudaGetSymbolAddress(&pSums, g_sums);
    cudaGetSymbolAddress(&pCnt,  g_cnt);

    const int TB = 256;
    auto cdiv = [](long long a, long long b) { return (int)((a + b - 1) / b); };
    cudaStream_t s2 = g_side.s;

    // ===== Fork: CSR build on side stream, GEMM1 on main stream =====
    cudaEventRecord(g_side.fork, 0);
    cudaStreamWaitEvent(s2, g_side.fork, 0);

    cudaMemsetAsync(pDegi, 0, (size_t)n * sizeof(int), s2);
    cudaMemsetAsync(pSums, 0, (size_t)G * 64 * sizeof(float), s2);
    cudaMemsetAsync(pCnt,  0, (size_t)G * sizeof(float), s2);
    degi_kernel<<<cdiv(E, TB), TB, 0, s2>>>(dst, E);
    scan_reduce_kernel<<<nb, 512, 0, s2>>>(n);
    scan_write_kernel<<<nb, 512, 0, s2>>>(n);
    csr_fill_kernel<<<cdiv(E, TB), TB, 0, s2>>>(src, dst, E);
    cudaEventRecord(g_side.join, s2);

    sgemm_kernel<0><<<dim3(1, cdiv(n, 128)), TB>>>(x, W1, (float*)pBufA, n, 64, 128, nullptr, nullptr);

    // ===== Join, then layer 1: GCNConv(128 -> 64) + relu (fused) =====
    cudaStreamWaitEvent(0, g_side.join, 0);
    gcn_gather_kernel<<<cdiv((long long)n * 32, TB), TB>>>(b1, n);

    // ===== Layer 2: GATConv(64 -> 64, heads=2, concat) + relu =====
    sgemm_kernel<2><<<dim3(2, cdiv(n, 128)), TB>>>((const float*)pBufB, W2, (float*)pBufA, n, 128, 64, as2, ad2);
    gat_gather_kernel<2, 64, true><<<cdiv((long long)n * 32, TB), TB>>>(b2, n, (float*)pBufB);

    // ===== Layer 3: GATConv(128 -> 64, heads=1, mean) =====
    sgemm_kernel<1><<<dim3(1, cdiv(n, 128)), TB>>>((const float*)pBufB, W3, (float*)pBufA, n, 64, 128, as3, ad3);
    gat_gather_kernel<1, 64, false><<<cdiv((long long)n * 32, TB), TB>>>(b3, n, (float*)pBufB);

    // ===== Mean pool + FC + log_softmax =====
    pool_kernel<<<cdiv((long long)n * 16, TB), TB>>>(bat, n);
    final_kernel<<<cdiv(G, TB), TB>>>(Wfc, bfc, (float*)d_out, G);
}